// round 5
// baseline (speedup 1.0000x reference)
#include <cuda_runtime.h>
#include <cuda_fp16.h>
#include <math.h>

// ---------------- static problem sizes (from reference setup_inputs) -------
#define NMAX 100352      // >= N=100000
#define EMAX 1000448     // >= E=1000000
#define DF   64          // input feature dim
#define DF2  32          // half2 elements per row
#define HH   128         // hidden
#define HHF  64          // H/2
#define CCH  40          // classes

#define PBLOCKS 264      // persistent grid: <=2 blocks/SM on a >=132-SM part
#define PWARPS  (PBLOCKS * 8)

// ---------------- device scratch (no allocations allowed) ------------------
__device__ float   g_F1 [NMAX * DF];    // phase-1 result -> phase-2 feat_0 (fp32)
__device__ float   g_F2 [NMAX * DF];    // phase-2 result (h) -> MLP input (fp32)
__device__ __half2 g_FSa[NMAX * DF2];   // scaled feature ping (fp16)
__device__ __half2 g_FSb[NMAX * DF2];   // scaled feature pong (fp16)
__device__ float   g_t1 [NMAX * HH];    // MLP intermediate
__device__ float   g_t2 [NMAX * HHF];   // MLP intermediate
__device__ int     g_din [NMAX];
__device__ int     g_dout[NMAX];
__device__ int     g_cur [NMAX];
__device__ int     g_rowptr[NMAX];
__device__ int     g_csrc[EMAX];
__device__ float   g_snorm[NMAX];
__device__ float   g_dnorm[NMAX];
__device__ int     g_total;
__device__ int          g_count;        // grid-barrier arrive counter
__device__ volatile int g_sense;        // grid-barrier phase

// ---------------- preprocessing kernels ------------------------------------
__global__ void zero_kernel(int n) {
    int i = blockIdx.x * blockDim.x + threadIdx.x;
    if (i < n) { g_din[i] = 0; g_dout[i] = 0; g_cur[i] = 0; }
    if (i == 0) { g_total = 0; g_count = 0; g_sense = 0; }
}

__global__ void deg_kernel(const int* __restrict__ src, const int* __restrict__ dst, int e) {
    int i = blockIdx.x * blockDim.x + threadIdx.x;
    if (i < e) {
        atomicAdd(&g_dout[src[i]], 1);
        atomicAdd(&g_din [dst[i]], 1);
    }
}

__global__ void norm_kernel(int n) {
    int i = blockIdx.x * blockDim.x + threadIdx.x;
    if (i < n) {
        int o = g_dout[i];
        int d = g_din[i];
        g_snorm[i] = (o > 0) ? rsqrtf((float)o) : 0.0f;
        g_dnorm[i] = (d > 0) ? rsqrtf((float)d) : 0.0f;
    }
}

// Assign each node a contiguous span of size din[i] via warp-aggregated atomic.
__global__ void offset_kernel(int n) {
    int i = blockIdx.x * blockDim.x + threadIdx.x;
    int lane = threadIdx.x & 31;
    int d = (i < n) ? g_din[i] : 0;
    int x = d;
#pragma unroll
    for (int off = 1; off < 32; off <<= 1) {
        int y = __shfl_up_sync(0xffffffffu, x, off);
        if (lane >= off) x += y;
    }
    int tot = __shfl_sync(0xffffffffu, x, 31);
    int base = 0;
    if (lane == 31) base = atomicAdd(&g_total, tot);
    base = __shfl_sync(0xffffffffu, base, 31);
    if (i < n) g_rowptr[i] = base + x - d;   // exclusive prefix within warp
}

__global__ void scatter_kernel(const int* __restrict__ src, const int* __restrict__ dst, int e) {
    int i = blockIdx.x * blockDim.x + threadIdx.x;
    if (i < e) {
        int d = dst[i];
        int p = g_rowptr[d] + atomicAdd(&g_cur[d], 1);
        g_csrc[p] = src[i];
    }
}

__global__ void initfs_kernel(const float* __restrict__ feat, int n) {
    int i = blockIdx.x * blockDim.x + threadIdx.x;   // one half2 per thread
    if (i < n * DF2) {
        int node = i >> 5;
        float sn = g_snorm[node];
        float2 v = *(const float2*)(feat + 2 * (size_t)i);
        g_FSa[i] = __float22half2_rn(make_float2(v.x * sn, v.y * sn));
    }
}

// ---------------- grid-wide software barrier --------------------------------
__device__ __forceinline__ void grid_sync(int phase) {
    __syncthreads();
    if (threadIdx.x == 0) {
        __threadfence();
        if (atomicAdd(&g_count, 1) == PBLOCKS - 1) {
            g_count = 0;           // reset BEFORE release so next barrier is clean
            __threadfence();
            g_sense = phase;       // release
        } else {
            while (g_sense < phase) __nanosleep(40);
            __threadfence();       // acquire
        }
    }
    __syncthreads();
}

// ---------------- fused 20-step APPNP (persistent, warp-per-node) ----------
// Steps 0..9:  f0 = feat (fp32); step 9 also writes unscaled f to g_F1.
// Steps 10..19: f0 = g_F1;       step 19 also writes unscaled f to g_F2.
// Scaled fp16 features ping-pong g_FSa <-> g_FSb; grid barrier between steps.
__global__ __launch_bounds__(256, 2) void appnp_fused(const float* __restrict__ feat, int n) {
    int wid  = blockIdx.x * 8 + (threadIdx.x >> 5);
    int lane = threadIdx.x & 31;                    // lane owns half2 column `lane`
    int npw  = (n + PWARPS - 1) / PWARPS;
    int nbeg = wid * npw;
    int nend = min(nbeg + npw, n);

    for (int step = 0; step < 20; step++) {
        const __half2* __restrict__ fs_in  = (step & 1) ? g_FSb : g_FSa;
        __half2*       __restrict__ fs_out = (step & 1) ? g_FSa : g_FSb;
        const float*   __restrict__ f0     = (step < 10) ? feat : g_F1;

        for (int node = nbeg; node < nend; node++) {
            int beg = g_rowptr[node];               // L1-resident after step 0
            int end = beg + g_din[node];

            float a0x = 0.f, a0y = 0.f, a1x = 0.f, a1y = 0.f;
            float a2x = 0.f, a2y = 0.f, a3x = 0.f, a3y = 0.f;
            int e = beg;
            for (; e + 8 <= end; e += 8) {
                int s0 = __ldg(&g_csrc[e]);
                int s1 = __ldg(&g_csrc[e + 1]);
                int s2 = __ldg(&g_csrc[e + 2]);
                int s3 = __ldg(&g_csrc[e + 3]);
                int s4 = __ldg(&g_csrc[e + 4]);
                int s5 = __ldg(&g_csrc[e + 5]);
                int s6 = __ldg(&g_csrc[e + 6]);
                int s7 = __ldg(&g_csrc[e + 7]);
                // __ldcg: L2-only — keep the random row stream out of L1
                float2 v0 = __half22float2(__ldcg(&fs_in[(size_t)s0 * DF2 + lane]));
                float2 v1 = __half22float2(__ldcg(&fs_in[(size_t)s1 * DF2 + lane]));
                float2 v2 = __half22float2(__ldcg(&fs_in[(size_t)s2 * DF2 + lane]));
                float2 v3 = __half22float2(__ldcg(&fs_in[(size_t)s3 * DF2 + lane]));
                float2 v4 = __half22float2(__ldcg(&fs_in[(size_t)s4 * DF2 + lane]));
                float2 v5 = __half22float2(__ldcg(&fs_in[(size_t)s5 * DF2 + lane]));
                float2 v6 = __half22float2(__ldcg(&fs_in[(size_t)s6 * DF2 + lane]));
                float2 v7 = __half22float2(__ldcg(&fs_in[(size_t)s7 * DF2 + lane]));
                a0x += v0.x; a0y += v0.y; a1x += v1.x; a1y += v1.y;
                a2x += v2.x; a2y += v2.y; a3x += v3.x; a3y += v3.y;
                a0x += v4.x; a0y += v4.y; a1x += v5.x; a1y += v5.y;
                a2x += v6.x; a2y += v6.y; a3x += v7.x; a3y += v7.y;
            }
            for (; e < end; e++) {
                int s = __ldg(&g_csrc[e]);
                float2 v = __half22float2(__ldcg(&fs_in[(size_t)s * DF2 + lane]));
                a0x += v.x; a0y += v.y;
            }
            float ax = (a0x + a1x) + (a2x + a3x);
            float ay = (a0y + a1y) + (a2y + a3y);

            float dn = g_dnorm[node];
            float sn = g_snorm[node];
            size_t o = (size_t)node * DF + 2 * lane;
            float2 f0v = *(const float2*)(f0 + o);
            float fx = 0.9f * ax * dn + 0.1f * f0v.x;
            float fy = 0.9f * ay * dn + 0.1f * f0v.y;

            fs_out[(size_t)node * DF2 + lane] = __float22half2_rn(make_float2(fx * sn, fy * sn));
            if (step == 9)  *(float2*)(g_F1 + o) = make_float2(fx, fy);
            if (step == 19) *(float2*)(g_F2 + o) = make_float2(fx, fy);
        }

        if (step < 19) grid_sync(step + 1);   // no barrier after the last step
    }
}

// ---------------- register-tiled SGEMM: C = [relu](A[MxK] @ W[KxNC] + b) ----
template<int K, int NC, bool RELU>
__global__ __launch_bounds__(256) void gemm_tiled(const float* __restrict__ A,
                                                  const float* __restrict__ W,
                                                  const float* __restrict__ bias,
                                                  float* __restrict__ C, int M) {
    constexpr int TX = NC / 4;       // 32 (NC=128) or 16 (NC=64)
    constexpr int TY = 256 / TX;     // 8 or 16
    constexpr int TM = 64 / TY;      // 8 or 4
    __shared__ float sAT[32][66];    // [k][row]
    __shared__ float sW[32][NC];

    int tid = threadIdx.x;
    int tx = tid % TX;
    int ty = tid / TX;
    int rowBase = blockIdx.x * 64;

    float acc[TM][4];
#pragma unroll
    for (int m = 0; m < TM; m++)
#pragma unroll
        for (int j = 0; j < 4; j++) acc[m][j] = 0.0f;

    for (int kk = 0; kk < K; kk += 32) {
        for (int i = tid; i < 64 * 32; i += 256) {
            int r = i >> 5, k = i & 31;
            int gr = rowBase + r;
            sAT[k][r] = (gr < M) ? A[(size_t)gr * K + kk + k] : 0.0f;
        }
        for (int i = tid; i < 32 * NC; i += 256) {
            int k = i / NC, c = i % NC;
            sW[k][c] = W[(size_t)(kk + k) * NC + c];
        }
        __syncthreads();
#pragma unroll
        for (int k = 0; k < 32; k++) {
            float4 w = *(const float4*)&sW[k][tx * 4];
            float a[TM];
#pragma unroll
            for (int m2 = 0; m2 < TM / 2; m2++) {
                float2 t = *(const float2*)&sAT[k][ty * TM + 2 * m2];
                a[2 * m2] = t.x; a[2 * m2 + 1] = t.y;
            }
#pragma unroll
            for (int m = 0; m < TM; m++) {
                acc[m][0] += a[m] * w.x;
                acc[m][1] += a[m] * w.y;
                acc[m][2] += a[m] * w.z;
                acc[m][3] += a[m] * w.w;
            }
        }
        __syncthreads();
    }

    float4 bv = *(const float4*)&bias[tx * 4];
#pragma unroll
    for (int m = 0; m < TM; m++) {
        int gr = rowBase + ty * TM + m;
        if (gr < M) {
            float4 v;
            v.x = acc[m][0] + bv.x;
            v.y = acc[m][1] + bv.y;
            v.z = acc[m][2] + bv.z;
            v.w = acc[m][3] + bv.w;
            if (RELU) {
                v.x = fmaxf(v.x, 0.0f); v.y = fmaxf(v.y, 0.0f);
                v.z = fmaxf(v.z, 0.0f); v.w = fmaxf(v.w, 0.0f);
            }
            *(float4*)&C[(size_t)gr * NC + tx * 4] = v;
        }
    }
}

// naive GEMM kept for the small head layer (K=64, NC=40)
template<int K, int NC, bool RELU>
__global__ __launch_bounds__(256) void gemm_small(const float* __restrict__ A,
                                                  const float* __restrict__ W,
                                                  const float* __restrict__ bias,
                                                  float* __restrict__ C, int M) {
    __shared__ float sA[64][33];
    __shared__ float sW[32][NC];
    const int CPT = NC / 4;
    float acc[CPT];
    int tid = threadIdx.x;
    int r  = tid >> 2;
    int cg = tid & 3;
    int row = blockIdx.x * 64 + r;
#pragma unroll
    for (int c = 0; c < CPT; c++) acc[c] = 0.0f;

    for (int kk = 0; kk < K; kk += 32) {
        for (int i = tid; i < 64 * 32; i += 256) {
            int rr = i >> 5, kx = i & 31;
            int grow = blockIdx.x * 64 + rr;
            sA[rr][kx] = (grow < M) ? A[(size_t)grow * K + kk + kx] : 0.0f;
        }
        for (int i = tid; i < 32 * NC; i += 256) {
            int kx = i / NC, cx = i % NC;
            sW[kx][cx] = W[(size_t)(kk + kx) * NC + cx];
        }
        __syncthreads();
#pragma unroll
        for (int k = 0; k < 32; k++) {
            float a = sA[r][k];
#pragma unroll
            for (int c = 0; c < CPT; c++) acc[c] += a * sW[k][c * 4 + cg];
        }
        __syncthreads();
    }

    if (row < M) {
#pragma unroll
        for (int c = 0; c < CPT; c++) {
            float v = acc[c] + bias[c * 4 + cg];
            if (RELU) v = fmaxf(v, 0.0f);
            C[(size_t)row * NC + c * 4 + cg] = v;
        }
    }
}

// ---------------- launch ----------------------------------------------------
extern "C" void kernel_launch(void* const* d_in, const int* in_sizes, int n_in,
                              void* d_out, int out_size) {
    const float* feat = (const float*)d_in[0];
    const int*   src  = (const int*)  d_in[1];
    const int*   dst  = (const int*)  d_in[2];
    const float* W1   = (const float*)d_in[3];
    const float* b1   = (const float*)d_in[4];
    const float* W2   = (const float*)d_in[5];
    const float* b2   = (const float*)d_in[6];
    const float* Wh1  = (const float*)d_in[7];
    const float* bh1  = (const float*)d_in[8];
    const float* Wh2  = (const float*)d_in[9];
    const float* bh2  = (const float*)d_in[10];
    float* out = (float*)d_out;

    int n = in_sizes[0] / DF;
    int e = in_sizes[1];

    void *pF2, *pT1, *pT2;
    cudaGetSymbolAddress(&pF2, g_F2);
    cudaGetSymbolAddress(&pT1, g_t1);
    cudaGetSymbolAddress(&pT2, g_t2);
    float* F2 = (float*)pF2;
    float* T1 = (float*)pT1;
    float* T2 = (float*)pT2;

    // --- CSR build + norms (fresh every launch; no caching allowed) ---
    zero_kernel   <<<(n + 255) / 256, 256>>>(n);
    deg_kernel    <<<(e + 255) / 256, 256>>>(src, dst, e);
    norm_kernel   <<<(n + 255) / 256, 256>>>(n);
    offset_kernel <<<(n + 255) / 256, 256>>>(n);
    scatter_kernel<<<(e + 255) / 256, 256>>>(src, dst, e);
    initfs_kernel <<<(n * DF2 + 255) / 256, 256>>>(feat, n);

    // --- all 20 propagation steps in one persistent kernel ---
    appnp_fused<<<PBLOCKS, 256>>>(feat, n);

    // --- MLP trunk + head (fp32 SGEMMs) ---
    float* h_last = out + (size_t)n * CCH;   // d_out = [out (N*40)] [h_last (N*128)]
    int gb = (n + 63) / 64;
    gemm_tiled<DF,  HH,  true ><<<gb, 256>>>(F2,     W1,  b1,  T1,     n);
    gemm_tiled<HH,  HH,  false><<<gb, 256>>>(T1,     W2,  b2,  h_last, n);
    gemm_tiled<HH,  HHF, true ><<<gb, 256>>>(h_last, Wh1, bh1, T2,     n);
    gemm_small<HHF, CCH, false><<<gb, 256>>>(T2,     Wh2, bh2, out,    n);
}

// round 6
// speedup vs baseline: 1.5679x; 1.5679x over previous
#include <cuda_runtime.h>
#include <cuda_fp16.h>
#include <math.h>

// ---------------- static problem sizes (from reference setup_inputs) -------
#define NMAX 100352      // >= N=100000
#define EMAX 1000448     // >= E=1000000
#define DF   64          // input feature dim
#define DF2  32          // half2 elements per row
#define HH   128         // hidden
#define HHF  64          // H/2
#define CCH  40          // classes

// ---------------- device scratch (no allocations allowed) ------------------
__device__ float   g_F1 [NMAX * DF];    // phase-1 result -> phase-2 feat_0 (fp32)
__device__ float   g_F2 [NMAX * DF];    // phase-2 result (h) -> MLP input (fp32)
__device__ __half2 g_FSa[NMAX * DF2];   // scaled feature ping (fp16)
__device__ __half2 g_FSb[NMAX * DF2];   // scaled feature pong (fp16)
__device__ float   g_t1 [NMAX * HH];    // MLP intermediate
__device__ float   g_t2 [NMAX * HHF];   // MLP intermediate
__device__ int     g_din [NMAX];
__device__ int     g_dout[NMAX];
__device__ int     g_cur [NMAX];
__device__ int     g_rowptr[NMAX];
__device__ int     g_csrc[EMAX];
__device__ float   g_snorm[NMAX];
__device__ float   g_dnorm[NMAX];
__device__ int     g_total;
__device__ int          g_count;        // grid-barrier arrive counter
__device__ volatile int g_sense;        // grid-barrier phase

// ---------------- preprocessing kernels ------------------------------------
__global__ void zero_kernel(int n) {
    int i = blockIdx.x * blockDim.x + threadIdx.x;
    if (i < n) { g_din[i] = 0; g_dout[i] = 0; g_cur[i] = 0; }
    if (i == 0) { g_total = 0; g_count = 0; g_sense = 0; }
}

__global__ void deg_kernel(const int* __restrict__ src, const int* __restrict__ dst, int e) {
    int i = blockIdx.x * blockDim.x + threadIdx.x;
    if (i < e) {
        atomicAdd(&g_dout[src[i]], 1);
        atomicAdd(&g_din [dst[i]], 1);
    }
}

__global__ void norm_kernel(int n) {
    int i = blockIdx.x * blockDim.x + threadIdx.x;
    if (i < n) {
        int o = g_dout[i];
        int d = g_din[i];
        g_snorm[i] = (o > 0) ? rsqrtf((float)o) : 0.0f;
        g_dnorm[i] = (d > 0) ? rsqrtf((float)d) : 0.0f;
    }
}

// Assign each node a contiguous span of size din[i] via warp-aggregated atomic.
__global__ void offset_kernel(int n) {
    int i = blockIdx.x * blockDim.x + threadIdx.x;
    int lane = threadIdx.x & 31;
    int d = (i < n) ? g_din[i] : 0;
    int x = d;
#pragma unroll
    for (int off = 1; off < 32; off <<= 1) {
        int y = __shfl_up_sync(0xffffffffu, x, off);
        if (lane >= off) x += y;
    }
    int tot = __shfl_sync(0xffffffffu, x, 31);
    int base = 0;
    if (lane == 31) base = atomicAdd(&g_total, tot);
    base = __shfl_sync(0xffffffffu, base, 31);
    if (i < n) g_rowptr[i] = base + x - d;   // exclusive prefix within warp
}

__global__ void scatter_kernel(const int* __restrict__ src, const int* __restrict__ dst, int e) {
    int i = blockIdx.x * blockDim.x + threadIdx.x;
    if (i < e) {
        int d = dst[i];
        int p = g_rowptr[d] + atomicAdd(&g_cur[d], 1);
        g_csrc[p] = src[i];
    }
}

__global__ void initfs_kernel(const float* __restrict__ feat, int n) {
    int i = blockIdx.x * blockDim.x + threadIdx.x;   // one half2 per thread
    if (i < n * DF2) {
        int node = i >> 5;
        float sn = g_snorm[node];
        float2 v = *(const float2*)(feat + 2 * (size_t)i);
        g_FSa[i] = __float22half2_rn(make_float2(v.x * sn, v.y * sn));
    }
}

// ---------------- grid-wide software barrier (all blocks co-resident) -------
__device__ __forceinline__ void grid_sync(int phase) {
    __syncthreads();
    if (threadIdx.x == 0) {
        __threadfence();
        if (atomicAdd(&g_count, 1) == (int)gridDim.x - 1) {
            g_count = 0;           // reset BEFORE release so next barrier is clean
            __threadfence();
            g_sense = phase;       // release
        } else {
            while (g_sense < phase) __nanosleep(40);
            __threadfence();       // acquire
        }
    }
    __syncthreads();
}

// ---------------- fused 20-step APPNP (persistent, warp-per-node) ----------
// Steps 0..9:  f0 = feat (fp32); step 9 also writes unscaled f to g_F1.
// Steps 10..19: f0 = g_F1;       step 19 also writes unscaled f to g_F2.
// Scaled fp16 features ping-pong g_FSa <-> g_FSb; grid barrier between steps.
// launch_bounds(256,4): <=64 regs -> 4 blocks/SM = 32 warps/SM resident.
__global__ __launch_bounds__(256, 4) void appnp_fused(const float* __restrict__ feat, int n) {
    int nwarps = gridDim.x * 8;
    int wid  = blockIdx.x * 8 + (threadIdx.x >> 5);
    int lane = threadIdx.x & 31;                    // lane owns half2 column `lane`
    int npw  = (n + nwarps - 1) / nwarps;
    int nbeg = wid * npw;
    int nend = min(nbeg + npw, n);

    for (int step = 0; step < 20; step++) {
        const __half2* __restrict__ fs_in  = (step & 1) ? g_FSb : g_FSa;
        __half2*       __restrict__ fs_out = (step & 1) ? g_FSa : g_FSb;
        const float*   __restrict__ f0     = (step < 10) ? feat : g_F1;

        for (int node = nbeg; node < nend; node++) {
            int beg = g_rowptr[node];               // L1-resident after step 0
            int end = beg + g_din[node];

            float a0x = 0.f, a0y = 0.f, a1x = 0.f, a1y = 0.f;
            float a2x = 0.f, a2y = 0.f, a3x = 0.f, a3y = 0.f;
            int e = beg;
            for (; e + 8 <= end; e += 8) {
                int s0 = __ldg(&g_csrc[e]);
                int s1 = __ldg(&g_csrc[e + 1]);
                int s2 = __ldg(&g_csrc[e + 2]);
                int s3 = __ldg(&g_csrc[e + 3]);
                int s4 = __ldg(&g_csrc[e + 4]);
                int s5 = __ldg(&g_csrc[e + 5]);
                int s6 = __ldg(&g_csrc[e + 6]);
                int s7 = __ldg(&g_csrc[e + 7]);
                // __ldcg: L2-only — keep the random row stream out of L1
                float2 v0 = __half22float2(__ldcg(&fs_in[(size_t)s0 * DF2 + lane]));
                float2 v1 = __half22float2(__ldcg(&fs_in[(size_t)s1 * DF2 + lane]));
                float2 v2 = __half22float2(__ldcg(&fs_in[(size_t)s2 * DF2 + lane]));
                float2 v3 = __half22float2(__ldcg(&fs_in[(size_t)s3 * DF2 + lane]));
                float2 v4 = __half22float2(__ldcg(&fs_in[(size_t)s4 * DF2 + lane]));
                float2 v5 = __half22float2(__ldcg(&fs_in[(size_t)s5 * DF2 + lane]));
                float2 v6 = __half22float2(__ldcg(&fs_in[(size_t)s6 * DF2 + lane]));
                float2 v7 = __half22float2(__ldcg(&fs_in[(size_t)s7 * DF2 + lane]));
                a0x += v0.x; a0y += v0.y; a1x += v1.x; a1y += v1.y;
                a2x += v2.x; a2y += v2.y; a3x += v3.x; a3y += v3.y;
                a0x += v4.x; a0y += v4.y; a1x += v5.x; a1y += v5.y;
                a2x += v6.x; a2y += v6.y; a3x += v7.x; a3y += v7.y;
            }
            for (; e < end; e++) {
                int s = __ldg(&g_csrc[e]);
                float2 v = __half22float2(__ldcg(&fs_in[(size_t)s * DF2 + lane]));
                a0x += v.x; a0y += v.y;
            }
            float ax = (a0x + a1x) + (a2x + a3x);
            float ay = (a0y + a1y) + (a2y + a3y);

            float dn = g_dnorm[node];
            float sn = g_snorm[node];
            size_t o = (size_t)node * DF + 2 * lane;
            float2 f0v = *(const float2*)(f0 + o);
            float fx = 0.9f * ax * dn + 0.1f * f0v.x;
            float fy = 0.9f * ay * dn + 0.1f * f0v.y;

            fs_out[(size_t)node * DF2 + lane] = __float22half2_rn(make_float2(fx * sn, fy * sn));
            if (step == 9)  *(float2*)(g_F1 + o) = make_float2(fx, fy);
            if (step == 19) *(float2*)(g_F2 + o) = make_float2(fx, fy);
        }

        if (step < 19) grid_sync(step + 1);   // no barrier after the last step
    }
}

// ---------------- register-tiled SGEMM: C = [relu](A[MxK] @ W[KxNC] + b) ----
template<int K, int NC, bool RELU>
__global__ __launch_bounds__(256) void gemm_tiled(const float* __restrict__ A,
                                                  const float* __restrict__ W,
                                                  const float* __restrict__ bias,
                                                  float* __restrict__ C, int M) {
    constexpr int TX = NC / 4;       // 32 (NC=128) or 16 (NC=64)
    constexpr int TY = 256 / TX;     // 8 or 16
    constexpr int TM = 64 / TY;      // 8 or 4
    __shared__ float sAT[32][66];    // [k][row]
    __shared__ float sW[32][NC];

    int tid = threadIdx.x;
    int tx = tid % TX;
    int ty = tid / TX;
    int rowBase = blockIdx.x * 64;

    float acc[TM][4];
#pragma unroll
    for (int m = 0; m < TM; m++)
#pragma unroll
        for (int j = 0; j < 4; j++) acc[m][j] = 0.0f;

    for (int kk = 0; kk < K; kk += 32) {
        for (int i = tid; i < 64 * 32; i += 256) {
            int r = i >> 5, k = i & 31;
            int gr = rowBase + r;
            sAT[k][r] = (gr < M) ? A[(size_t)gr * K + kk + k] : 0.0f;
        }
        for (int i = tid; i < 32 * NC; i += 256) {
            int k = i / NC, c = i % NC;
            sW[k][c] = W[(size_t)(kk + k) * NC + c];
        }
        __syncthreads();
#pragma unroll
        for (int k = 0; k < 32; k++) {
            float4 w = *(const float4*)&sW[k][tx * 4];
            float a[TM];
#pragma unroll
            for (int m2 = 0; m2 < TM / 2; m2++) {
                float2 t = *(const float2*)&sAT[k][ty * TM + 2 * m2];
                a[2 * m2] = t.x; a[2 * m2 + 1] = t.y;
            }
#pragma unroll
            for (int m = 0; m < TM; m++) {
                acc[m][0] += a[m] * w.x;
                acc[m][1] += a[m] * w.y;
                acc[m][2] += a[m] * w.z;
                acc[m][3] += a[m] * w.w;
            }
        }
        __syncthreads();
    }

    float4 bv = *(const float4*)&bias[tx * 4];
#pragma unroll
    for (int m = 0; m < TM; m++) {
        int gr = rowBase + ty * TM + m;
        if (gr < M) {
            float4 v;
            v.x = acc[m][0] + bv.x;
            v.y = acc[m][1] + bv.y;
            v.z = acc[m][2] + bv.z;
            v.w = acc[m][3] + bv.w;
            if (RELU) {
                v.x = fmaxf(v.x, 0.0f); v.y = fmaxf(v.y, 0.0f);
                v.z = fmaxf(v.z, 0.0f); v.w = fmaxf(v.w, 0.0f);
            }
            *(float4*)&C[(size_t)gr * NC + tx * 4] = v;
        }
    }
}

// naive GEMM kept for the small head layer (K=64, NC=40)
template<int K, int NC, bool RELU>
__global__ __launch_bounds__(256) void gemm_small(const float* __restrict__ A,
                                                  const float* __restrict__ W,
                                                  const float* __restrict__ bias,
                                                  float* __restrict__ C, int M) {
    __shared__ float sA[64][33];
    __shared__ float sW[32][NC];
    const int CPT = NC / 4;
    float acc[CPT];
    int tid = threadIdx.x;
    int r  = tid >> 2;
    int cg = tid & 3;
    int row = blockIdx.x * 64 + r;
#pragma unroll
    for (int c = 0; c < CPT; c++) acc[c] = 0.0f;

    for (int kk = 0; kk < K; kk += 32) {
        for (int i = tid; i < 64 * 32; i += 256) {
            int rr = i >> 5, kx = i & 31;
            int grow = blockIdx.x * 64 + rr;
            sA[rr][kx] = (grow < M) ? A[(size_t)grow * K + kk + kx] : 0.0f;
        }
        for (int i = tid; i < 32 * NC; i += 256) {
            int kx = i / NC, cx = i % NC;
            sW[kx][cx] = W[(size_t)(kk + kx) * NC + cx];
        }
        __syncthreads();
#pragma unroll
        for (int k = 0; k < 32; k++) {
            float a = sA[r][k];
#pragma unroll
            for (int c = 0; c < CPT; c++) acc[c] += a * sW[k][c * 4 + cg];
        }
        __syncthreads();
    }

    if (row < M) {
#pragma unroll
        for (int c = 0; c < CPT; c++) {
            float v = acc[c] + bias[c * 4 + cg];
            if (RELU) v = fmaxf(v, 0.0f);
            C[(size_t)row * NC + c * 4 + cg] = v;
        }
    }
}

// ---------------- launch ----------------------------------------------------
extern "C" void kernel_launch(void* const* d_in, const int* in_sizes, int n_in,
                              void* d_out, int out_size) {
    const float* feat = (const float*)d_in[0];
    const int*   src  = (const int*)  d_in[1];
    const int*   dst  = (const int*)  d_in[2];
    const float* W1   = (const float*)d_in[3];
    const float* b1   = (const float*)d_in[4];
    const float* W2   = (const float*)d_in[5];
    const float* b2   = (const float*)d_in[6];
    const float* Wh1  = (const float*)d_in[7];
    const float* bh1  = (const float*)d_in[8];
    const float* Wh2  = (const float*)d_in[9];
    const float* bh2  = (const float*)d_in[10];
    float* out = (float*)d_out;

    int n = in_sizes[0] / DF;
    int e = in_sizes[1];

    void *pF2, *pT1, *pT2;
    cudaGetSymbolAddress(&pF2, g_F2);
    cudaGetSymbolAddress(&pT1, g_t1);
    cudaGetSymbolAddress(&pT2, g_t2);
    float* F2 = (float*)pF2;
    float* T1 = (float*)pT1;
    float* T2 = (float*)pT2;

    // persistent grid sized to EXACT one co-resident wave (deadlock-free barrier)
    int dev = 0, sms = 0, occ = 0;
    cudaGetDevice(&dev);
    cudaDeviceGetAttribute(&sms, cudaDevAttrMultiProcessorCount, dev);
    cudaOccupancyMaxActiveBlocksPerMultiprocessor(&occ, appnp_fused, 256, 0);
    if (occ < 1) occ = 1;
    int pblocks = sms * occ;

    // --- CSR build + norms (fresh every launch; no caching allowed) ---
    zero_kernel   <<<(n + 255) / 256, 256>>>(n);
    deg_kernel    <<<(e + 255) / 256, 256>>>(src, dst, e);
    norm_kernel   <<<(n + 255) / 256, 256>>>(n);
    offset_kernel <<<(n + 255) / 256, 256>>>(n);
    scatter_kernel<<<(e + 255) / 256, 256>>>(src, dst, e);
    initfs_kernel <<<(n * DF2 + 255) / 256, 256>>>(feat, n);

    // --- all 20 propagation steps in one persistent kernel ---
    appnp_fused<<<pblocks, 256>>>(feat, n);

    // --- MLP trunk + head (fp32 SGEMMs) ---
    float* h_last = out + (size_t)n * CCH;   // d_out = [out (N*40)] [h_last (N*128)]
    int gb = (n + 63) / 64;
    gemm_tiled<DF,  HH,  true ><<<gb, 256>>>(F2,     W1,  b1,  T1,     n);
    gemm_tiled<HH,  HH,  false><<<gb, 256>>>(T1,     W2,  b2,  h_last, n);
    gemm_tiled<HH,  HHF, true ><<<gb, 256>>>(h_last, Wh1, bh1, T2,     n);
    gemm_small<HHF, CCH, false><<<gb, 256>>>(T2,     Wh2, bh2, out,    n);
}

// round 7
// speedup vs baseline: 1.8824x; 1.2006x over previous
#include <cuda_runtime.h>
#include <cuda_fp16.h>
#include <math.h>

// ---------------- static problem sizes (from reference setup_inputs) -------
#define NMAX 100352      // >= N=100000
#define EMAX 1000448     // >= E=1000000
#define DF   64          // input feature dim
#define DF2  32          // half2 elements per row
#define HH   128         // hidden
#define HHF  64          // H/2
#define CCH  40          // classes

// ---------------- device scratch (no allocations allowed) ------------------
__device__ float   g_F1 [NMAX * DF];    // phase-1 result -> phase-2 feat_0 (fp32)
__device__ float   g_F2 [NMAX * DF];    // phase-2 result (h) -> MLP input (fp32)
__device__ __half2 g_FSa[NMAX * DF2];   // scaled feature ping (fp16)
__device__ __half2 g_FSb[NMAX * DF2];   // scaled feature pong (fp16)
__device__ float   g_t1 [NMAX * HH];    // MLP intermediate
__device__ float   g_t2 [NMAX * HHF];   // MLP intermediate
__device__ int     g_din [NMAX];
__device__ int     g_dout[NMAX];
__device__ int     g_cur [NMAX];
__device__ int     g_rowptr[NMAX];
__device__ int     g_csrc[EMAX];
__device__ float   g_snorm[NMAX];
__device__ float   g_dnorm[NMAX];
__device__ int     g_total;
__device__ int          g_count;        // grid-barrier arrive counter
__device__ volatile int g_sense;        // grid-barrier phase

// ---------------- launch 1: zero --------------------------------------------
__global__ void zero_kernel(int n) {
    int i = blockIdx.x * blockDim.x + threadIdx.x;
    if (i < n) { g_din[i] = 0; g_dout[i] = 0; g_cur[i] = 0; }
    if (i == 0) { g_total = 0; g_count = 0; g_sense = 0; }
}

// ---------------- launch 2: degree histogram --------------------------------
__global__ void deg_kernel(const int* __restrict__ src, const int* __restrict__ dst, int e) {
    int i = blockIdx.x * blockDim.x + threadIdx.x;
    if (i < e) {
        atomicAdd(&g_dout[src[i]], 1);
        atomicAdd(&g_din [dst[i]], 1);
    }
}

// ---------------- grid-wide software barrier (all blocks co-resident) -------
__device__ __forceinline__ void grid_sync(int phase) {
    __syncthreads();
    if (threadIdx.x == 0) {
        __threadfence();
        if (atomicAdd(&g_count, 1) == (int)gridDim.x - 1) {
            g_count = 0;
            __threadfence();
            g_sense = phase;       // release
        } else {
            while (g_sense < phase) __nanosleep(40);
            __threadfence();       // acquire
        }
    }
    __syncthreads();
}

// ---------------- launch 3: fused finalize ----------------------------------
// Phase A: norms + CSR span offsets (warp-aggregated atomic, unordered spans).
// grid barrier (offsets of ALL nodes must exist before scatter).
// Phase B: scatter edges into CSR. Phase C: build fp16 scaled feature buffer.
__global__ __launch_bounds__(256) void finalize_kernel(const int* __restrict__ src,
                                                       const int* __restrict__ dst,
                                                       const float* __restrict__ feat,
                                                       int n, int e) {
    int gtid = blockIdx.x * blockDim.x + threadIdx.x;
    int stride = gridDim.x * blockDim.x;
    int lane = threadIdx.x & 31;

    // ---- phase A: norms + offsets (all warps run same #iters; shuffles safe)
    for (int base = 0; base < n; base += stride) {
        int i = base + gtid;
        int d = 0;
        if (i < n) {
            int o = g_dout[i];
            d = g_din[i];
            g_snorm[i] = (o > 0) ? rsqrtf((float)o) : 0.0f;
            g_dnorm[i] = (d > 0) ? rsqrtf((float)d) : 0.0f;
        }
        int x = d;
#pragma unroll
        for (int off = 1; off < 32; off <<= 1) {
            int y = __shfl_up_sync(0xffffffffu, x, off);
            if (lane >= off) x += y;
        }
        int tot = __shfl_sync(0xffffffffu, x, 31);
        int bofs = 0;
        if (lane == 31 && tot > 0) bofs = atomicAdd(&g_total, tot);
        bofs = __shfl_sync(0xffffffffu, bofs, 31);
        if (i < n) g_rowptr[i] = bofs + x - d;
    }

    grid_sync(1);

    // ---- phase B: scatter edges
    for (int i = gtid; i < e; i += stride) {
        int dd = dst[i];
        int p = g_rowptr[dd] + atomicAdd(&g_cur[dd], 1);
        g_csrc[p] = src[i];
    }

    // ---- phase C: fp16 scaled feature init (needs only phase-A snorm)
    int n32 = n * DF2;
    for (int i = gtid; i < n32; i += stride) {
        int node = i >> 5;
        float sn = g_snorm[node];
        float2 v = *(const float2*)(feat + 2 * (size_t)i);
        g_FSa[i] = __float22half2_rn(make_float2(v.x * sn, v.y * sn));
    }
}

// ---------------- APPNP propagation step (warp-per-node, pull/CSR) ---------
// Gathers fp16-scaled rows, accumulates fp32.
// FO: 0 none, 1 -> also write unscaled fp32 f into g_F1, 2 -> into g_F2
template<int FO>
__global__ __launch_bounds__(256) void appnp_step(const float* __restrict__ f0,
                                                  const __half2* __restrict__ fs_in,
                                                  __half2* __restrict__ fs_out,
                                                  int n) {
    int node = blockIdx.x * 8 + (threadIdx.x >> 5);
    if (node >= n) return;
    int lane = threadIdx.x & 31;          // lane owns half2 column `lane`

    int beg = g_rowptr[node];
    int end = beg + g_din[node];

    float a0x = 0.f, a0y = 0.f, a1x = 0.f, a1y = 0.f;
    float a2x = 0.f, a2y = 0.f, a3x = 0.f, a3y = 0.f;
    int e = beg;
    for (; e + 8 <= end; e += 8) {        // 8 independent 128B row-reads in flight
        int s0 = __ldg(&g_csrc[e]);
        int s1 = __ldg(&g_csrc[e + 1]);
        int s2 = __ldg(&g_csrc[e + 2]);
        int s3 = __ldg(&g_csrc[e + 3]);
        int s4 = __ldg(&g_csrc[e + 4]);
        int s5 = __ldg(&g_csrc[e + 5]);
        int s6 = __ldg(&g_csrc[e + 6]);
        int s7 = __ldg(&g_csrc[e + 7]);
        float2 v0 = __half22float2(__ldcg(&fs_in[(size_t)s0 * DF2 + lane]));
        float2 v1 = __half22float2(__ldcg(&fs_in[(size_t)s1 * DF2 + lane]));
        float2 v2 = __half22float2(__ldcg(&fs_in[(size_t)s2 * DF2 + lane]));
        float2 v3 = __half22float2(__ldcg(&fs_in[(size_t)s3 * DF2 + lane]));
        float2 v4 = __half22float2(__ldcg(&fs_in[(size_t)s4 * DF2 + lane]));
        float2 v5 = __half22float2(__ldcg(&fs_in[(size_t)s5 * DF2 + lane]));
        float2 v6 = __half22float2(__ldcg(&fs_in[(size_t)s6 * DF2 + lane]));
        float2 v7 = __half22float2(__ldcg(&fs_in[(size_t)s7 * DF2 + lane]));
        a0x += v0.x; a0y += v0.y; a1x += v1.x; a1y += v1.y;
        a2x += v2.x; a2y += v2.y; a3x += v3.x; a3y += v3.y;
        a0x += v4.x; a0y += v4.y; a1x += v5.x; a1y += v5.y;
        a2x += v6.x; a2y += v6.y; a3x += v7.x; a3y += v7.y;
    }
    for (; e < end; e++) {
        int s = __ldg(&g_csrc[e]);
        float2 v = __half22float2(__ldcg(&fs_in[(size_t)s * DF2 + lane]));
        a0x += v.x; a0y += v.y;
    }
    float ax = (a0x + a1x) + (a2x + a3x);
    float ay = (a0y + a1y) + (a2y + a3y);

    float dn = g_dnorm[node];
    float sn = g_snorm[node];
    size_t o = (size_t)node * DF + 2 * lane;
    float2 f0v = *(const float2*)(f0 + o);
    float fx = 0.9f * ax * dn + 0.1f * f0v.x;
    float fy = 0.9f * ay * dn + 0.1f * f0v.y;

    fs_out[(size_t)node * DF2 + lane] = __float22half2_rn(make_float2(fx * sn, fy * sn));
    if (FO == 1) *(float2*)(g_F1 + o) = make_float2(fx, fy);
    if (FO == 2) *(float2*)(g_F2 + o) = make_float2(fx, fy);
}

// ---------------- register-tiled SGEMM: C = [relu](A[MxK] @ W[KxNC] + b) ----
template<int K, int NC, bool RELU>
__global__ __launch_bounds__(256) void gemm_tiled(const float* __restrict__ A,
                                                  const float* __restrict__ W,
                                                  const float* __restrict__ bias,
                                                  float* __restrict__ C, int M) {
    constexpr int TX = NC / 4;       // 32 (NC=128) or 16 (NC=64)
    constexpr int TY = 256 / TX;     // 8 or 16
    constexpr int TM = 64 / TY;      // 8 or 4
    __shared__ float sAT[32][66];    // [k][row]
    __shared__ float sW[32][NC];

    int tid = threadIdx.x;
    int tx = tid % TX;
    int ty = tid / TX;
    int rowBase = blockIdx.x * 64;

    float acc[TM][4];
#pragma unroll
    for (int m = 0; m < TM; m++)
#pragma unroll
        for (int j = 0; j < 4; j++) acc[m][j] = 0.0f;

    for (int kk = 0; kk < K; kk += 32) {
        for (int i = tid; i < 64 * 32; i += 256) {
            int r = i >> 5, k = i & 31;
            int gr = rowBase + r;
            sAT[k][r] = (gr < M) ? A[(size_t)gr * K + kk + k] : 0.0f;
        }
        for (int i = tid; i < 32 * NC; i += 256) {
            int k = i / NC, c = i % NC;
            sW[k][c] = W[(size_t)(kk + k) * NC + c];
        }
        __syncthreads();
#pragma unroll
        for (int k = 0; k < 32; k++) {
            float4 w = *(const float4*)&sW[k][tx * 4];
            float a[TM];
#pragma unroll
            for (int m2 = 0; m2 < TM / 2; m2++) {
                float2 t = *(const float2*)&sAT[k][ty * TM + 2 * m2];
                a[2 * m2] = t.x; a[2 * m2 + 1] = t.y;
            }
#pragma unroll
            for (int m = 0; m < TM; m++) {
                acc[m][0] += a[m] * w.x;
                acc[m][1] += a[m] * w.y;
                acc[m][2] += a[m] * w.z;
                acc[m][3] += a[m] * w.w;
            }
        }
        __syncthreads();
    }

    float4 bv = *(const float4*)&bias[tx * 4];
#pragma unroll
    for (int m = 0; m < TM; m++) {
        int gr = rowBase + ty * TM + m;
        if (gr < M) {
            float4 v;
            v.x = acc[m][0] + bv.x;
            v.y = acc[m][1] + bv.y;
            v.z = acc[m][2] + bv.z;
            v.w = acc[m][3] + bv.w;
            if (RELU) {
                v.x = fmaxf(v.x, 0.0f); v.y = fmaxf(v.y, 0.0f);
                v.z = fmaxf(v.z, 0.0f); v.w = fmaxf(v.w, 0.0f);
            }
            *(float4*)&C[(size_t)gr * NC + tx * 4] = v;
        }
    }
}

// naive GEMM kept for the small head layer (K=64, NC=40)
template<int K, int NC, bool RELU>
__global__ __launch_bounds__(256) void gemm_small(const float* __restrict__ A,
                                                  const float* __restrict__ W,
                                                  const float* __restrict__ bias,
                                                  float* __restrict__ C, int M) {
    __shared__ float sA[64][33];
    __shared__ float sW[32][NC];
    const int CPT = NC / 4;
    float acc[CPT];
    int tid = threadIdx.x;
    int r  = tid >> 2;
    int cg = tid & 3;
    int row = blockIdx.x * 64 + r;
#pragma unroll
    for (int c = 0; c < CPT; c++) acc[c] = 0.0f;

    for (int kk = 0; kk < K; kk += 32) {
        for (int i = tid; i < 64 * 32; i += 256) {
            int rr = i >> 5, kx = i & 31;
            int grow = blockIdx.x * 64 + rr;
            sA[rr][kx] = (grow < M) ? A[(size_t)grow * K + kk + kx] : 0.0f;
        }
        for (int i = tid; i < 32 * NC; i += 256) {
            int kx = i / NC, cx = i % NC;
            sW[kx][cx] = W[(size_t)(kk + kx) * NC + cx];
        }
        __syncthreads();
#pragma unroll
        for (int k = 0; k < 32; k++) {
            float a = sA[r][k];
#pragma unroll
            for (int c = 0; c < CPT; c++) acc[c] += a * sW[k][c * 4 + cg];
        }
        __syncthreads();
    }

    if (row < M) {
#pragma unroll
        for (int c = 0; c < CPT; c++) {
            float v = acc[c] + bias[c * 4 + cg];
            if (RELU) v = fmaxf(v, 0.0f);
            C[(size_t)row * NC + c * 4 + cg] = v;
        }
    }
}

// ---------------- launch ----------------------------------------------------
extern "C" void kernel_launch(void* const* d_in, const int* in_sizes, int n_in,
                              void* d_out, int out_size) {
    const float* feat = (const float*)d_in[0];
    const int*   src  = (const int*)  d_in[1];
    const int*   dst  = (const int*)  d_in[2];
    const float* W1   = (const float*)d_in[3];
    const float* b1   = (const float*)d_in[4];
    const float* W2   = (const float*)d_in[5];
    const float* b2   = (const float*)d_in[6];
    const float* Wh1  = (const float*)d_in[7];
    const float* bh1  = (const float*)d_in[8];
    const float* Wh2  = (const float*)d_in[9];
    const float* bh2  = (const float*)d_in[10];
    float* out = (float*)d_out;

    int n = in_sizes[0] / DF;
    int e = in_sizes[1];

    void *pF1, *pF2, *pFa, *pFb, *pT1, *pT2;
    cudaGetSymbolAddress(&pF1, g_F1);
    cudaGetSymbolAddress(&pF2, g_F2);
    cudaGetSymbolAddress(&pFa, g_FSa);
    cudaGetSymbolAddress(&pFb, g_FSb);
    cudaGetSymbolAddress(&pT1, g_t1);
    cudaGetSymbolAddress(&pT2, g_t2);
    float*   F1  = (float*)pF1;
    float*   F2  = (float*)pF2;
    __half2* FSa = (__half2*)pFa;
    __half2* FSb = (__half2*)pFb;
    float*   T1  = (float*)pT1;
    float*   T2  = (float*)pT2;

    // exact one co-resident wave for finalize's internal grid barrier
    int dev = 0, sms = 0, occ = 0;
    cudaGetDevice(&dev);
    cudaDeviceGetAttribute(&sms, cudaDevAttrMultiProcessorCount, dev);
    cudaOccupancyMaxActiveBlocksPerMultiprocessor(&occ, finalize_kernel, 256, 0);
    if (occ < 1) occ = 1;
    int fblocks = sms * occ;

    // --- preprocessing: exactly 3 launches (4th launch = appnp_step #0) ---
    zero_kernel    <<<(n + 255) / 256, 256>>>(n);
    deg_kernel     <<<(e + 255) / 256, 256>>>(src, dst, e);
    finalize_kernel<<<fblocks, 256>>>(src, dst, feat, n, e);

    // --- 20 propagation steps (2 APPNP phases of K=10) ---
    int step_blocks = (n + 7) / 8;  // 8 warps (nodes) per 256-thread block
    __half2* fin = FSa; __half2* fout = FSb;
    for (int s = 0; s < 10; s++) {
        if (s == 9) appnp_step<1><<<step_blocks, 256>>>(feat, fin, fout, n);
        else        appnp_step<0><<<step_blocks, 256>>>(feat, fin, fout, n);
        __half2* t = fin; fin = fout; fout = t;
    }
    for (int s = 0; s < 10; s++) {
        if (s == 9) appnp_step<2><<<step_blocks, 256>>>(F1, fin, fout, n);
        else        appnp_step<0><<<step_blocks, 256>>>(F1, fin, fout, n);
        __half2* t = fin; fin = fout; fout = t;
    }

    // --- MLP trunk + head (fp32 SGEMMs) ---
    float* h_last = out + (size_t)n * CCH;   // d_out = [out (N*40)] [h_last (N*128)]
    int gb = (n + 63) / 64;
    gemm_tiled<DF,  HH,  true ><<<gb, 256>>>(F2,     W1,  b1,  T1,     n);
    gemm_tiled<HH,  HH,  false><<<gb, 256>>>(T1,     W2,  b2,  h_last, n);
    gemm_tiled<HH,  HHF, true ><<<gb, 256>>>(h_last, Wh1, bh1, T2,     n);
    gemm_small<HHF, CCH, false><<<gb, 256>>>(T2,     Wh2, bh2, out,    n);
}

// round 8
// speedup vs baseline: 2.1386x; 1.1361x over previous
#include <cuda_runtime.h>
#include <cuda_fp16.h>
#include <math.h>

// ---------------- static problem sizes (from reference setup_inputs) -------
#define NMAX 100352      // >= N=100000
#define EMAX 1000448     // >= E=1000000
#define DF   64          // input feature dim
#define DF2  32          // half2 elements per row
#define ROWB 128         // bytes per fp16 feature row
#define HH   128         // hidden
#define HHF  64          // H/2
#define CCH  40          // classes

// ---------------- device scratch (no allocations allowed) ------------------
__device__ float   g_F1 [NMAX * DF];    // phase-1 result -> phase-2 feat_0 (fp32)
__device__ float   g_F2 [NMAX * DF];    // phase-2 result (h) -> MLP input (fp32)
__device__ __half2 g_FSa[NMAX * DF2];   // scaled feature ping (fp16)
__device__ __half2 g_FSb[NMAX * DF2];   // scaled feature pong (fp16)
__device__ float   g_t1 [NMAX * HH];    // MLP intermediate
__device__ float   g_t2 [NMAX * HHF];   // MLP intermediate
__device__ int     g_din [NMAX];
__device__ int     g_dout[NMAX];
__device__ int     g_cur [NMAX];
__device__ int     g_rowptr[NMAX];
__device__ int     g_csrc[EMAX];        // BYTE offsets (src*128), not indices
__device__ float   g_snorm[NMAX];
__device__ float   g_dnorm[NMAX];
__device__ int     g_total;
__device__ int          g_count;        // grid-barrier arrive counter
__device__ volatile int g_sense;        // grid-barrier phase

__device__ __forceinline__ __half2 u2h(unsigned int u) {
    return *reinterpret_cast<__half2*>(&u);
}

// ---------------- launch 1: zero --------------------------------------------
__global__ void zero_kernel(int n) {
    int i = blockIdx.x * blockDim.x + threadIdx.x;
    if (i < n) { g_din[i] = 0; g_dout[i] = 0; g_cur[i] = 0; }
    if (i == 0) { g_total = 0; g_count = 0; g_sense = 0; }
}

// ---------------- launch 2: degree histogram --------------------------------
__global__ void deg_kernel(const int* __restrict__ src, const int* __restrict__ dst, int e) {
    int i = blockIdx.x * blockDim.x + threadIdx.x;
    if (i < e) {
        atomicAdd(&g_dout[src[i]], 1);
        atomicAdd(&g_din [dst[i]], 1);
    }
}

// ---------------- grid-wide software barrier (all blocks co-resident) -------
__device__ __forceinline__ void grid_sync(int phase) {
    __syncthreads();
    if (threadIdx.x == 0) {
        __threadfence();
        if (atomicAdd(&g_count, 1) == (int)gridDim.x - 1) {
            g_count = 0;
            __threadfence();
            g_sense = phase;       // release
        } else {
            while (g_sense < phase) __nanosleep(40);
            __threadfence();       // acquire
        }
    }
    __syncthreads();
}

// ---------------- launch 3: fused finalize ----------------------------------
// Phase A: norms + CSR span offsets. barrier. Phase B: scatter (stores BYTE
// offsets src*128). Phase C: fp16 scaled feature init.
__global__ __launch_bounds__(256) void finalize_kernel(const int* __restrict__ src,
                                                       const int* __restrict__ dst,
                                                       const float* __restrict__ feat,
                                                       int n, int e) {
    int gtid = blockIdx.x * blockDim.x + threadIdx.x;
    int stride = gridDim.x * blockDim.x;
    int lane = threadIdx.x & 31;

    for (int base = 0; base < n; base += stride) {
        int i = base + gtid;
        int d = 0;
        if (i < n) {
            int o = g_dout[i];
            d = g_din[i];
            g_snorm[i] = (o > 0) ? rsqrtf((float)o) : 0.0f;
            g_dnorm[i] = (d > 0) ? rsqrtf((float)d) : 0.0f;
        }
        int x = d;
#pragma unroll
        for (int off = 1; off < 32; off <<= 1) {
            int y = __shfl_up_sync(0xffffffffu, x, off);
            if (lane >= off) x += y;
        }
        int tot = __shfl_sync(0xffffffffu, x, 31);
        int bofs = 0;
        if (lane == 31 && tot > 0) bofs = atomicAdd(&g_total, tot);
        bofs = __shfl_sync(0xffffffffu, bofs, 31);
        if (i < n) g_rowptr[i] = bofs + x - d;
    }

    grid_sync(1);

    for (int i = gtid; i < e; i += stride) {
        int dd = dst[i];
        int p = g_rowptr[dd] + atomicAdd(&g_cur[dd], 1);
        g_csrc[p] = src[i] << 7;           // byte offset into 128B-row buffer
    }

    int n32 = n * DF2;
    for (int i = gtid; i < n32; i += stride) {
        int node = i >> 5;
        float sn = g_snorm[node];
        float2 v = *(const float2*)(feat + 2 * (size_t)i);
        g_FSa[i] = __float22half2_rn(make_float2(v.x * sn, v.y * sn));
    }
}

// ---------------- APPNP propagation step (warp-per-node, pull/CSR) ---------
// Half-warp edge pairing: lanes 0-15 gather edge e, lanes 16-31 edge e+1;
// each lane loads 8B (4 cols). One-level HADD2 pre-reduction, fp32 accumulate.
// FO: 0 none, 1 -> also write unscaled fp32 f into g_F1, 2 -> into g_F2
template<int FO>
__global__ __launch_bounds__(256) void appnp_step(const float* __restrict__ f0,
                                                  const __half2* __restrict__ fs_in,
                                                  __half2* __restrict__ fs_out,
                                                  int n) {
    int node = blockIdx.x * 8 + (threadIdx.x >> 5);
    if (node >= n) return;
    int lane = threadIdx.x & 31;
    int half = lane >> 4;                 // which edge of the pair
    int l16  = lane & 15;                 // lane's 8B chunk within the row
    const char* base = (const char*)fs_in + l16 * 8;

    int beg = g_rowptr[node];
    int end = beg + g_din[node];

    float2 aX = make_float2(0.f, 0.f);    // cols 4*l16, 4*l16+1
    float2 aY = make_float2(0.f, 0.f);    // cols 4*l16+2, 4*l16+3
    int e = beg;
    for (; e + 8 <= end; e += 8) {        // 8 edges per warp-iteration
        int oa = __ldg(&g_csrc[e     + half]);
        int ob = __ldg(&g_csrc[e + 2 + half]);
        int oc = __ldg(&g_csrc[e + 4 + half]);
        int od = __ldg(&g_csrc[e + 6 + half]);
        uint2 va = __ldcg((const uint2*)(base + oa));
        uint2 vb = __ldcg((const uint2*)(base + ob));
        uint2 vc = __ldcg((const uint2*)(base + oc));
        uint2 vd = __ldcg((const uint2*)(base + od));
        __half2 hx0 = __hadd2(u2h(va.x), u2h(vb.x));   // pairwise fp16 add
        __half2 hx1 = __hadd2(u2h(vc.x), u2h(vd.x));
        __half2 hy0 = __hadd2(u2h(va.y), u2h(vb.y));
        __half2 hy1 = __hadd2(u2h(vc.y), u2h(vd.y));
        float2 f;
        f = __half22float2(hx0); aX.x += f.x; aX.y += f.y;
        f = __half22float2(hx1); aX.x += f.x; aX.y += f.y;
        f = __half22float2(hy0); aY.x += f.x; aY.y += f.y;
        f = __half22float2(hy1); aY.x += f.x; aY.y += f.y;
    }
    for (; e + 2 <= end; e += 2) {        // paired tail (2 edges), no fp16 add
        int o = __ldg(&g_csrc[e + half]);
        uint2 v = __ldcg((const uint2*)(base + o));
        float2 f = __half22float2(u2h(v.x)); aX.x += f.x; aX.y += f.y;
        f = __half22float2(u2h(v.y)); aY.x += f.x; aY.y += f.y;
    }
    if (e < end && half == 0) {           // single leftover edge
        int o = __ldg(&g_csrc[e]);
        uint2 v = __ldcg((const uint2*)(base + o));
        float2 f = __half22float2(u2h(v.x)); aX.x += f.x; aX.y += f.y;
        f = __half22float2(u2h(v.y)); aY.x += f.x; aY.y += f.y;
    }
    // combine the two half-warps (both halves end with the full sum)
    aX.x += __shfl_xor_sync(0xffffffffu, aX.x, 16);
    aX.y += __shfl_xor_sync(0xffffffffu, aX.y, 16);
    aY.x += __shfl_xor_sync(0xffffffffu, aY.x, 16);
    aY.y += __shfl_xor_sync(0xffffffffu, aY.y, 16);

    if (half == 0) {                      // lanes 0-15 write the 128B row
        float dn = g_dnorm[node];
        float sn = g_snorm[node];
        float4 f0v = __ldg((const float4*)(f0 + (size_t)node * DF) + l16);
        float fx0 = 0.9f * aX.x * dn + 0.1f * f0v.x;
        float fx1 = 0.9f * aX.y * dn + 0.1f * f0v.y;
        float fx2 = 0.9f * aY.x * dn + 0.1f * f0v.z;
        float fx3 = 0.9f * aY.y * dn + 0.1f * f0v.w;

        __half2 h0 = __floats2half2_rn(fx0 * sn, fx1 * sn);
        __half2 h1 = __floats2half2_rn(fx2 * sn, fx3 * sn);
        uint2 w;
        w.x = *reinterpret_cast<unsigned int*>(&h0);
        w.y = *reinterpret_cast<unsigned int*>(&h1);
        *((uint2*)((char*)fs_out + (size_t)node * ROWB) + l16) = w;

        if (FO == 1) ((float4*)(g_F1 + (size_t)node * DF))[l16] = make_float4(fx0, fx1, fx2, fx3);
        if (FO == 2) ((float4*)(g_F2 + (size_t)node * DF))[l16] = make_float4(fx0, fx1, fx2, fx3);
    }
}

// ---------------- register-tiled SGEMM: C = [relu](A[MxK] @ W[KxNC] + b) ----
template<int K, int NC, bool RELU>
__global__ __launch_bounds__(256) void gemm_tiled(const float* __restrict__ A,
                                                  const float* __restrict__ W,
                                                  const float* __restrict__ bias,
                                                  float* __restrict__ C, int M) {
    constexpr int TX = NC / 4;       // 32 (NC=128) or 16 (NC=64)
    constexpr int TY = 256 / TX;     // 8 or 16
    constexpr int TM = 64 / TY;      // 8 or 4
    __shared__ float sAT[32][66];    // [k][row]
    __shared__ float sW[32][NC];

    int tid = threadIdx.x;
    int tx = tid % TX;
    int ty = tid / TX;
    int rowBase = blockIdx.x * 64;

    float acc[TM][4];
#pragma unroll
    for (int m = 0; m < TM; m++)
#pragma unroll
        for (int j = 0; j < 4; j++) acc[m][j] = 0.0f;

    for (int kk = 0; kk < K; kk += 32) {
        for (int i = tid; i < 64 * 32; i += 256) {
            int r = i >> 5, k = i & 31;
            int gr = rowBase + r;
            sAT[k][r] = (gr < M) ? A[(size_t)gr * K + kk + k] : 0.0f;
        }
        for (int i = tid; i < 32 * NC; i += 256) {
            int k = i / NC, c = i % NC;
            sW[k][c] = W[(size_t)(kk + k) * NC + c];
        }
        __syncthreads();
#pragma unroll
        for (int k = 0; k < 32; k++) {
            float4 w = *(const float4*)&sW[k][tx * 4];
            float a[TM];
#pragma unroll
            for (int m2 = 0; m2 < TM / 2; m2++) {
                float2 t = *(const float2*)&sAT[k][ty * TM + 2 * m2];
                a[2 * m2] = t.x; a[2 * m2 + 1] = t.y;
            }
#pragma unroll
            for (int m = 0; m < TM; m++) {
                acc[m][0] += a[m] * w.x;
                acc[m][1] += a[m] * w.y;
                acc[m][2] += a[m] * w.z;
                acc[m][3] += a[m] * w.w;
            }
        }
        __syncthreads();
    }

    float4 bv = *(const float4*)&bias[tx * 4];
#pragma unroll
    for (int m = 0; m < TM; m++) {
        int gr = rowBase + ty * TM + m;
        if (gr < M) {
            float4 v;
            v.x = acc[m][0] + bv.x;
            v.y = acc[m][1] + bv.y;
            v.z = acc[m][2] + bv.z;
            v.w = acc[m][3] + bv.w;
            if (RELU) {
                v.x = fmaxf(v.x, 0.0f); v.y = fmaxf(v.y, 0.0f);
                v.z = fmaxf(v.z, 0.0f); v.w = fmaxf(v.w, 0.0f);
            }
            *(float4*)&C[(size_t)gr * NC + tx * 4] = v;
        }
    }
}

// naive GEMM kept for the small head layer (K=64, NC=40)
template<int K, int NC, bool RELU>
__global__ __launch_bounds__(256) void gemm_small(const float* __restrict__ A,
                                                  const float* __restrict__ W,
                                                  const float* __restrict__ bias,
                                                  float* __restrict__ C, int M) {
    __shared__ float sA[64][33];
    __shared__ float sW[32][NC];
    const int CPT = NC / 4;
    float acc[CPT];
    int tid = threadIdx.x;
    int r  = tid >> 2;
    int cg = tid & 3;
    int row = blockIdx.x * 64 + r;
#pragma unroll
    for (int c = 0; c < CPT; c++) acc[c] = 0.0f;

    for (int kk = 0; kk < K; kk += 32) {
        for (int i = tid; i < 64 * 32; i += 256) {
            int rr = i >> 5, kx = i & 31;
            int grow = blockIdx.x * 64 + rr;
            sA[rr][kx] = (grow < M) ? A[(size_t)grow * K + kk + kx] : 0.0f;
        }
        for (int i = tid; i < 32 * NC; i += 256) {
            int kx = i / NC, cx = i % NC;
            sW[kx][cx] = W[(size_t)(kk + kx) * NC + cx];
        }
        __syncthreads();
#pragma unroll
        for (int k = 0; k < 32; k++) {
            float a = sA[r][k];
#pragma unroll
            for (int c = 0; c < CPT; c++) acc[c] += a * sW[k][c * 4 + cg];
        }
        __syncthreads();
    }

    if (row < M) {
#pragma unroll
        for (int c = 0; c < CPT; c++) {
            float v = acc[c] + bias[c * 4 + cg];
            if (RELU) v = fmaxf(v, 0.0f);
            C[(size_t)row * NC + c * 4 + cg] = v;
        }
    }
}

// ---------------- launch ----------------------------------------------------
extern "C" void kernel_launch(void* const* d_in, const int* in_sizes, int n_in,
                              void* d_out, int out_size) {
    const float* feat = (const float*)d_in[0];
    const int*   src  = (const int*)  d_in[1];
    const int*   dst  = (const int*)  d_in[2];
    const float* W1   = (const float*)d_in[3];
    const float* b1   = (const float*)d_in[4];
    const float* W2   = (const float*)d_in[5];
    const float* b2   = (const float*)d_in[6];
    const float* Wh1  = (const float*)d_in[7];
    const float* bh1  = (const float*)d_in[8];
    const float* Wh2  = (const float*)d_in[9];
    const float* bh2  = (const float*)d_in[10];
    float* out = (float*)d_out;

    int n = in_sizes[0] / DF;
    int e = in_sizes[1];

    void *pF1, *pF2, *pFa, *pFb, *pT1, *pT2;
    cudaGetSymbolAddress(&pF1, g_F1);
    cudaGetSymbolAddress(&pF2, g_F2);
    cudaGetSymbolAddress(&pFa, g_FSa);
    cudaGetSymbolAddress(&pFb, g_FSb);
    cudaGetSymbolAddress(&pT1, g_t1);
    cudaGetSymbolAddress(&pT2, g_t2);
    float*   F1  = (float*)pF1;
    float*   F2  = (float*)pF2;
    __half2* FSa = (__half2*)pFa;
    __half2* FSb = (__half2*)pFb;
    float*   T1  = (float*)pT1;
    float*   T2  = (float*)pT2;

    // exact one co-resident wave for finalize's internal grid barrier
    int dev = 0, sms = 0, occ = 0;
    cudaGetDevice(&dev);
    cudaDeviceGetAttribute(&sms, cudaDevAttrMultiProcessorCount, dev);
    cudaOccupancyMaxActiveBlocksPerMultiprocessor(&occ, finalize_kernel, 256, 0);
    if (occ < 1) occ = 1;
    int fblocks = sms * occ;

    // --- preprocessing: exactly 3 launches (4th launch = appnp_step #0) ---
    zero_kernel    <<<(n + 255) / 256, 256>>>(n);
    deg_kernel     <<<(e + 255) / 256, 256>>>(src, dst, e);
    finalize_kernel<<<fblocks, 256>>>(src, dst, feat, n, e);

    // --- 20 propagation steps (2 APPNP phases of K=10) ---
    int step_blocks = (n + 7) / 8;  // 8 warps (nodes) per 256-thread block
    __half2* fin = FSa; __half2* fout = FSb;
    for (int s = 0; s < 10; s++) {
        if (s == 9) appnp_step<1><<<step_blocks, 256>>>(feat, fin, fout, n);
        else        appnp_step<0><<<step_blocks, 256>>>(feat, fin, fout, n);
        __half2* t = fin; fin = fout; fout = t;
    }
    for (int s = 0; s < 10; s++) {
        if (s == 9) appnp_step<2><<<step_blocks, 256>>>(F1, fin, fout, n);
        else        appnp_step<0><<<step_blocks, 256>>>(F1, fin, fout, n);
        __half2* t = fin; fin = fout; fout = t;
    }

    // --- MLP trunk + head (fp32 SGEMMs) ---
    float* h_last = out + (size_t)n * CCH;   // d_out = [out (N*40)] [h_last (N*128)]
    int gb = (n + 63) / 64;
    gemm_tiled<DF,  HH,  true ><<<gb, 256>>>(F2,     W1,  b1,  T1,     n);
    gemm_tiled<HH,  HH,  false><<<gb, 256>>>(T1,     W2,  b2,  h_last, n);
    gemm_tiled<HH,  HHF, true ><<<gb, 256>>>(h_last, Wh1, bh1, T2,     n);
    gemm_small<HHF, CCH, false><<<gb, 256>>>(T2,     Wh2, bh2, out,    n);
}

// round 9
// speedup vs baseline: 2.4465x; 1.1440x over previous
#include <cuda_runtime.h>
#include <cuda_fp16.h>
#include <math.h>

// ---------------- static problem sizes (from reference setup_inputs) -------
#define NMAX 100352      // >= N=100000
#define EMAX 1000448     // >= E=1000000
#define DF   64          // input feature dim
#define DF2  32          // half2 elements per row
#define ROWB 128         // bytes per fp16 feature row
#define HH   128         // hidden
#define HHF  64          // H/2
#define CCH  40          // classes
#define ALPHA 0.1f

// ---------------- device scratch (no allocations allowed) ------------------
__device__ float   g_F2 [NMAX * DF];    // phase-2 result (h) -> MLP input (fp32)
__device__ __half2 g_FSa[NMAX * DF2];   // scaled feature ping (fp16)
__device__ __half2 g_FSb[NMAX * DF2];   // scaled feature pong (fp16)
__device__ __half2 g_f0h[NMAX * DF2];   // alpha-premultiplied f0 (fp16); phase1=0.1*feat, phase2 written at step 9
__device__ float   g_t1 [NMAX * HH];    // MLP intermediate
__device__ float   g_t2 [NMAX * HHF];   // MLP intermediate
__device__ int     g_din [NMAX];
__device__ int     g_dout[NMAX];
__device__ int     g_cur [NMAX];
__device__ int     g_rowptr[NMAX];
__device__ int2    g_span[NMAX];        // (edge offset, degree) packed
__device__ int     g_csrc[EMAX];        // BYTE offsets (src*128), not indices
__device__ float   g_snorm[NMAX];
__device__ float   g_dnorm[NMAX];
__device__ int     g_total;
__device__ int          g_count;        // grid-barrier arrive counter
__device__ volatile int g_sense;        // grid-barrier phase

__device__ __forceinline__ __half2 u2h(unsigned int u) {
    return *reinterpret_cast<__half2*>(&u);
}

// ---------------- launch 1: zero --------------------------------------------
__global__ void zero_kernel(int n) {
    int i = blockIdx.x * blockDim.x + threadIdx.x;
    if (i < n) { g_din[i] = 0; g_dout[i] = 0; g_cur[i] = 0; }
    if (i == 0) { g_total = 0; g_count = 0; g_sense = 0; }
}

// ---------------- launch 2: degree histogram --------------------------------
__global__ void deg_kernel(const int* __restrict__ src, const int* __restrict__ dst, int e) {
    int i = blockIdx.x * blockDim.x + threadIdx.x;
    if (i < e) {
        atomicAdd(&g_dout[src[i]], 1);
        atomicAdd(&g_din [dst[i]], 1);
    }
}

// ---------------- grid-wide software barrier (all blocks co-resident) -------
__device__ __forceinline__ void grid_sync(int phase) {
    __syncthreads();
    if (threadIdx.x == 0) {
        __threadfence();
        if (atomicAdd(&g_count, 1) == (int)gridDim.x - 1) {
            g_count = 0;
            __threadfence();
            g_sense = phase;       // release
        } else {
            while (g_sense < phase) __nanosleep(40);
            __threadfence();       // acquire
        }
    }
    __syncthreads();
}

// ---------------- launch 3: fused finalize ----------------------------------
// Phase A: norms + CSR span offsets (+ packed span). barrier.
// Phase B: scatter edges (stores BYTE offsets src*128).
// Phase C: fp16 scaled feature init + alpha-premultiplied fp16 f0.
__global__ __launch_bounds__(256) void finalize_kernel(const int* __restrict__ src,
                                                       const int* __restrict__ dst,
                                                       const float* __restrict__ feat,
                                                       int n, int e) {
    int gtid = blockIdx.x * blockDim.x + threadIdx.x;
    int stride = gridDim.x * blockDim.x;
    int lane = threadIdx.x & 31;

    for (int base = 0; base < n; base += stride) {
        int i = base + gtid;
        int d = 0;
        if (i < n) {
            int o = g_dout[i];
            d = g_din[i];
            g_snorm[i] = (o > 0) ? rsqrtf((float)o) : 0.0f;
            g_dnorm[i] = (d > 0) ? rsqrtf((float)d) : 0.0f;
        }
        int x = d;
#pragma unroll
        for (int off = 1; off < 32; off <<= 1) {
            int y = __shfl_up_sync(0xffffffffu, x, off);
            if (lane >= off) x += y;
        }
        int tot = __shfl_sync(0xffffffffu, x, 31);
        int bofs = 0;
        if (lane == 31 && tot > 0) bofs = atomicAdd(&g_total, tot);
        bofs = __shfl_sync(0xffffffffu, bofs, 31);
        if (i < n) {
            int o = bofs + x - d;
            g_rowptr[i] = o;
            g_span[i] = make_int2(o, d);
        }
    }

    grid_sync(1);

    for (int i = gtid; i < e; i += stride) {
        int dd = dst[i];
        int p = g_rowptr[dd] + atomicAdd(&g_cur[dd], 1);
        g_csrc[p] = src[i] << 7;           // byte offset into 128B-row buffer
    }

    int n32 = n * DF2;
    for (int i = gtid; i < n32; i += stride) {
        int node = i >> 5;
        float sn = g_snorm[node];
        float2 v = *(const float2*)(feat + 2 * (size_t)i);
        g_FSa[i] = __float22half2_rn(make_float2(v.x * sn, v.y * sn));
        g_f0h[i] = __float22half2_rn(make_float2(ALPHA * v.x, ALPHA * v.y));
    }
}

// ---------------- APPNP propagation step (HALF-warp per node, pull/CSR) ----
// 16 lanes cover one 128B row (8B/lane). Each warp = 2 independent nodes
// (2 independent load chains, no cross-half reduction).
// FO: 0 none, 1 -> rewrite g_f0h in place (phase-2 anchor), 2 -> write g_F2.
template<int FO>
__global__ __launch_bounds__(256) void appnp_step(const __half2* __restrict__ fs_in,
                                                  __half2* __restrict__ fs_out,
                                                  int n) {
    int node = blockIdx.x * 16 + (threadIdx.x >> 4);
    if (node >= n) return;
    int l16 = threadIdx.x & 15;           // lane's 8B chunk within the row
    const char* base = (const char*)fs_in + l16 * 8;

    int2 span = __ldg(&g_span[node]);
    int e = span.x;
    int end = span.x + span.y;

    float ax0 = 0.f, ax1 = 0.f, ax2 = 0.f, ax3 = 0.f;
    for (; e + 4 <= end; e += 4) {        // 4 independent row-reads in flight/half
        int o0 = __ldg(&g_csrc[e]);
        int o1 = __ldg(&g_csrc[e + 1]);
        int o2 = __ldg(&g_csrc[e + 2]);
        int o3 = __ldg(&g_csrc[e + 3]);
        uint2 v0 = __ldcg((const uint2*)(base + o0));
        uint2 v1 = __ldcg((const uint2*)(base + o1));
        uint2 v2 = __ldcg((const uint2*)(base + o2));
        uint2 v3 = __ldcg((const uint2*)(base + o3));
        float2 f;
        f = __half22float2(u2h(v0.x)); ax0 += f.x; ax1 += f.y;
        f = __half22float2(u2h(v0.y)); ax2 += f.x; ax3 += f.y;
        f = __half22float2(u2h(v1.x)); ax0 += f.x; ax1 += f.y;
        f = __half22float2(u2h(v1.y)); ax2 += f.x; ax3 += f.y;
        f = __half22float2(u2h(v2.x)); ax0 += f.x; ax1 += f.y;
        f = __half22float2(u2h(v2.y)); ax2 += f.x; ax3 += f.y;
        f = __half22float2(u2h(v3.x)); ax0 += f.x; ax1 += f.y;
        f = __half22float2(u2h(v3.y)); ax2 += f.x; ax3 += f.y;
    }
    for (; e < end; e++) {
        int o = __ldg(&g_csrc[e]);
        uint2 v = __ldcg((const uint2*)(base + o));
        float2 f;
        f = __half22float2(u2h(v.x)); ax0 += f.x; ax1 += f.y;
        f = __half22float2(u2h(v.y)); ax2 += f.x; ax3 += f.y;
    }

    float dn = g_dnorm[node];
    float sn = g_snorm[node];
    float w = 0.9f * dn;

    uint2 f0u = *((const uint2*)((const char*)g_f0h + (size_t)node * ROWB) + l16);
    float2 f0a = __half22float2(u2h(f0u.x));
    float2 f0b = __half22float2(u2h(f0u.y));

    float fx0 = w * ax0 + f0a.x;
    float fx1 = w * ax1 + f0a.y;
    float fx2 = w * ax2 + f0b.x;
    float fx3 = w * ax3 + f0b.y;

    __half2 h0 = __floats2half2_rn(fx0 * sn, fx1 * sn);
    __half2 h1 = __floats2half2_rn(fx2 * sn, fx3 * sn);
    uint2 wv;
    wv.x = *reinterpret_cast<unsigned int*>(&h0);
    wv.y = *reinterpret_cast<unsigned int*>(&h1);
    *((uint2*)((char*)fs_out + (size_t)node * ROWB) + l16) = wv;

    if (FO == 1) {                        // becomes phase-2 anchor: 0.1*f in fp16
        __half2 a0 = __floats2half2_rn(ALPHA * fx0, ALPHA * fx1);
        __half2 a1 = __floats2half2_rn(ALPHA * fx2, ALPHA * fx3);
        uint2 av;
        av.x = *reinterpret_cast<unsigned int*>(&a0);
        av.y = *reinterpret_cast<unsigned int*>(&a1);
        *((uint2*)((char*)g_f0h + (size_t)node * ROWB) + l16) = av;
    }
    if (FO == 2) {                        // final h (fp32) for the MLP
        ((float4*)(g_F2 + (size_t)node * DF))[l16] = make_float4(fx0, fx1, fx2, fx3);
    }
}

// ---------------- register-tiled SGEMM: C = [relu](A[MxK] @ W[KxNC] + b) ----
template<int K, int NC, bool RELU>
__global__ __launch_bounds__(256) void gemm_tiled(const float* __restrict__ A,
                                                  const float* __restrict__ W,
                                                  const float* __restrict__ bias,
                                                  float* __restrict__ C, int M) {
    constexpr int TX = NC / 4;       // 32 (NC=128) or 16 (NC=64)
    constexpr int TY = 256 / TX;     // 8 or 16
    constexpr int TM = 64 / TY;      // 8 or 4
    __shared__ float sAT[32][66];    // [k][row]
    __shared__ float sW[32][NC];

    int tid = threadIdx.x;
    int tx = tid % TX;
    int ty = tid / TX;
    int rowBase = blockIdx.x * 64;

    float acc[TM][4];
#pragma unroll
    for (int m = 0; m < TM; m++)
#pragma unroll
        for (int j = 0; j < 4; j++) acc[m][j] = 0.0f;

    for (int kk = 0; kk < K; kk += 32) {
        for (int i = tid; i < 64 * 32; i += 256) {
            int r = i >> 5, k = i & 31;
            int gr = rowBase + r;
            sAT[k][r] = (gr < M) ? A[(size_t)gr * K + kk + k] : 0.0f;
        }
        for (int i = tid; i < 32 * NC; i += 256) {
            int k = i / NC, c = i % NC;
            sW[k][c] = W[(size_t)(kk + k) * NC + c];
        }
        __syncthreads();
#pragma unroll
        for (int k = 0; k < 32; k++) {
            float4 w = *(const float4*)&sW[k][tx * 4];
            float a[TM];
#pragma unroll
            for (int m2 = 0; m2 < TM / 2; m2++) {
                float2 t = *(const float2*)&sAT[k][ty * TM + 2 * m2];
                a[2 * m2] = t.x; a[2 * m2 + 1] = t.y;
            }
#pragma unroll
            for (int m = 0; m < TM; m++) {
                acc[m][0] += a[m] * w.x;
                acc[m][1] += a[m] * w.y;
                acc[m][2] += a[m] * w.z;
                acc[m][3] += a[m] * w.w;
            }
        }
        __syncthreads();
    }

    float4 bv = *(const float4*)&bias[tx * 4];
#pragma unroll
    for (int m = 0; m < TM; m++) {
        int gr = rowBase + ty * TM + m;
        if (gr < M) {
            float4 v;
            v.x = acc[m][0] + bv.x;
            v.y = acc[m][1] + bv.y;
            v.z = acc[m][2] + bv.z;
            v.w = acc[m][3] + bv.w;
            if (RELU) {
                v.x = fmaxf(v.x, 0.0f); v.y = fmaxf(v.y, 0.0f);
                v.z = fmaxf(v.z, 0.0f); v.w = fmaxf(v.w, 0.0f);
            }
            *(float4*)&C[(size_t)gr * NC + tx * 4] = v;
        }
    }
}

// naive GEMM kept for the small head layer (K=64, NC=40)
template<int K, int NC, bool RELU>
__global__ __launch_bounds__(256) void gemm_small(const float* __restrict__ A,
                                                  const float* __restrict__ W,
                                                  const float* __restrict__ bias,
                                                  float* __restrict__ C, int M) {
    __shared__ float sA[64][33];
    __shared__ float sW[32][NC];
    const int CPT = NC / 4;
    float acc[CPT];
    int tid = threadIdx.x;
    int r  = tid >> 2;
    int cg = tid & 3;
    int row = blockIdx.x * 64 + r;
#pragma unroll
    for (int c = 0; c < CPT; c++) acc[c] = 0.0f;

    for (int kk = 0; kk < K; kk += 32) {
        for (int i = tid; i < 64 * 32; i += 256) {
            int rr = i >> 5, kx = i & 31;
            int grow = blockIdx.x * 64 + rr;
            sA[rr][kx] = (grow < M) ? A[(size_t)grow * K + kk + kx] : 0.0f;
        }
        for (int i = tid; i < 32 * NC; i += 256) {
            int kx = i / NC, cx = i % NC;
            sW[kx][cx] = W[(size_t)(kk + kx) * NC + cx];
        }
        __syncthreads();
#pragma unroll
        for (int k = 0; k < 32; k++) {
            float a = sA[r][k];
#pragma unroll
            for (int c = 0; c < CPT; c++) acc[c] += a * sW[k][c * 4 + cg];
        }
        __syncthreads();
    }

    if (row < M) {
#pragma unroll
        for (int c = 0; c < CPT; c++) {
            float v = acc[c] + bias[c * 4 + cg];
            if (RELU) v = fmaxf(v, 0.0f);
            C[(size_t)row * NC + c * 4 + cg] = v;
        }
    }
}

// ---------------- launch ----------------------------------------------------
extern "C" void kernel_launch(void* const* d_in, const int* in_sizes, int n_in,
                              void* d_out, int out_size) {
    const float* feat = (const float*)d_in[0];
    const int*   src  = (const int*)  d_in[1];
    const int*   dst  = (const int*)  d_in[2];
    const float* W1   = (const float*)d_in[3];
    const float* b1   = (const float*)d_in[4];
    const float* W2   = (const float*)d_in[5];
    const float* b2   = (const float*)d_in[6];
    const float* Wh1  = (const float*)d_in[7];
    const float* bh1  = (const float*)d_in[8];
    const float* Wh2  = (const float*)d_in[9];
    const float* bh2  = (const float*)d_in[10];
    float* out = (float*)d_out;

    int n = in_sizes[0] / DF;
    int e = in_sizes[1];

    void *pF2, *pFa, *pFb, *pT1, *pT2;
    cudaGetSymbolAddress(&pF2, g_F2);
    cudaGetSymbolAddress(&pFa, g_FSa);
    cudaGetSymbolAddress(&pFb, g_FSb);
    cudaGetSymbolAddress(&pT1, g_t1);
    cudaGetSymbolAddress(&pT2, g_t2);
    float*   F2  = (float*)pF2;
    __half2* FSa = (__half2*)pFa;
    __half2* FSb = (__half2*)pFb;
    float*   T1  = (float*)pT1;
    float*   T2  = (float*)pT2;

    // exact one co-resident wave for finalize's internal grid barrier
    int dev = 0, sms = 0, occ = 0;
    cudaGetDevice(&dev);
    cudaDeviceGetAttribute(&sms, cudaDevAttrMultiProcessorCount, dev);
    cudaOccupancyMaxActiveBlocksPerMultiprocessor(&occ, finalize_kernel, 256, 0);
    if (occ < 1) occ = 1;
    int fblocks = sms * occ;

    // --- preprocessing: exactly 3 launches (4th launch = appnp_step #0) ---
    zero_kernel    <<<(n + 255) / 256, 256>>>(n);
    deg_kernel     <<<(e + 255) / 256, 256>>>(src, dst, e);
    finalize_kernel<<<fblocks, 256>>>(src, dst, feat, n, e);

    // --- 20 propagation steps (2 APPNP phases of K=10) ---
    int step_blocks = (n + 15) / 16;  // 16 half-warps (nodes) per 256-thread block
    __half2* fin = FSa; __half2* fout = FSb;
    for (int s = 0; s < 20; s++) {
        if      (s == 9)  appnp_step<1><<<step_blocks, 256>>>(fin, fout, n);
        else if (s == 19) appnp_step<2><<<step_blocks, 256>>>(fin, fout, n);
        else              appnp_step<0><<<step_blocks, 256>>>(fin, fout, n);
        __half2* t = fin; fin = fout; fout = t;
    }

    // --- MLP trunk + head (fp32 SGEMMs) ---
    float* h_last = out + (size_t)n * CCH;   // d_out = [out (N*40)] [h_last (N*128)]
    int gb = (n + 63) / 64;
    gemm_tiled<DF,  HH,  true ><<<gb, 256>>>(F2,     W1,  b1,  T1,     n);
    gemm_tiled<HH,  HH,  false><<<gb, 256>>>(T1,     W2,  b2,  h_last, n);
    gemm_tiled<HH,  HHF, true ><<<gb, 256>>>(h_last, Wh1, bh1, T2,     n);
    gemm_small<HHF, CCH, false><<<gb, 256>>>(T2,     Wh2, bh2, out,    n);
}

// round 10
// speedup vs baseline: 2.6403x; 1.0792x over previous
#include <cuda_runtime.h>
#include <cuda_fp16.h>
#include <math.h>

// ---------------- static problem sizes (from reference setup_inputs) -------
#define NMAX 100352      // >= N=100000
#define EMAX 1000448     // >= E=1000000
#define DF   64          // input feature dim
#define DF2  32          // half2 elements per row
#define ROWB 128         // bytes per fp16 feature row
#define HH   128         // hidden
#define HHF  64          // H/2
#define CCH  40          // classes
#define ALPHA 0.1f

// ---------------- device scratch (no allocations allowed) ------------------
__device__ float   g_F2 [NMAX * DF];    // phase-2 result (h) -> MLP input (fp32)
__device__ __half2 g_FSa[NMAX * DF2];   // scaled feature ping (fp16)
__device__ __half2 g_FSb[NMAX * DF2];   // scaled feature pong (fp16)
__device__ __half2 g_f0h[NMAX * DF2];   // alpha-premultiplied f0 (fp16)
__device__ float   g_t1 [NMAX * HH];    // MLP intermediate
__device__ float   g_t2 [NMAX * HHF];   // MLP intermediate
__device__ int     g_din [NMAX];
__device__ int     g_dout[NMAX];
__device__ int     g_cur [NMAX];
__device__ int     g_rowptr[NMAX];
__device__ int2    g_span[NMAX];        // (edge offset, degree) packed
__device__ int     g_csrc[EMAX];        // BYTE offsets (src*128), not indices
__device__ float   g_snorm[NMAX];
__device__ float   g_dnorm[NMAX];
__device__ int     g_total;
__device__ int          g_count;        // grid-barrier arrive counter
__device__ volatile int g_sense;        // grid-barrier phase

__device__ __forceinline__ __half2 u2h(unsigned int u) {
    return *reinterpret_cast<__half2*>(&u);
}

// ---------------- launch 1: zero --------------------------------------------
__global__ void zero_kernel(int n) {
    int i = blockIdx.x * blockDim.x + threadIdx.x;
    if (i < n) { g_din[i] = 0; g_dout[i] = 0; g_cur[i] = 0; }
    if (i == 0) { g_total = 0; g_count = 0; g_sense = 0; }
}

// ---------------- launch 2: degree histogram --------------------------------
__global__ void deg_kernel(const int* __restrict__ src, const int* __restrict__ dst, int e) {
    int i = blockIdx.x * blockDim.x + threadIdx.x;
    if (i < e) {
        atomicAdd(&g_dout[src[i]], 1);
        atomicAdd(&g_din [dst[i]], 1);
    }
}

// ---------------- grid-wide software barrier (all blocks co-resident) -------
__device__ __forceinline__ void grid_sync(int phase) {
    __syncthreads();
    if (threadIdx.x == 0) {
        __threadfence();
        if (atomicAdd(&g_count, 1) == (int)gridDim.x - 1) {
            g_count = 0;
            __threadfence();
            g_sense = phase;       // release
        } else {
            while (g_sense < phase) __nanosleep(40);
            __threadfence();       // acquire
        }
    }
    __syncthreads();
}

// ---------------- launch 3: fused finalize ----------------------------------
__global__ __launch_bounds__(256) void finalize_kernel(const int* __restrict__ src,
                                                       const int* __restrict__ dst,
                                                       const float* __restrict__ feat,
                                                       int n, int e) {
    int gtid = blockIdx.x * blockDim.x + threadIdx.x;
    int stride = gridDim.x * blockDim.x;
    int lane = threadIdx.x & 31;

    for (int base = 0; base < n; base += stride) {
        int i = base + gtid;
        int d = 0;
        if (i < n) {
            int o = g_dout[i];
            d = g_din[i];
            g_snorm[i] = (o > 0) ? rsqrtf((float)o) : 0.0f;
            g_dnorm[i] = (d > 0) ? rsqrtf((float)d) : 0.0f;
        }
        int x = d;
#pragma unroll
        for (int off = 1; off < 32; off <<= 1) {
            int y = __shfl_up_sync(0xffffffffu, x, off);
            if (lane >= off) x += y;
        }
        int tot = __shfl_sync(0xffffffffu, x, 31);
        int bofs = 0;
        if (lane == 31 && tot > 0) bofs = atomicAdd(&g_total, tot);
        bofs = __shfl_sync(0xffffffffu, bofs, 31);
        if (i < n) {
            int o = bofs + x - d;
            g_rowptr[i] = o;
            g_span[i] = make_int2(o, d);
        }
    }

    grid_sync(1);

    for (int i = gtid; i < e; i += stride) {
        int dd = dst[i];
        int p = g_rowptr[dd] + atomicAdd(&g_cur[dd], 1);
        g_csrc[p] = src[i] << 7;           // byte offset into 128B-row buffer
    }

    int n32 = n * DF2;
    for (int i = gtid; i < n32; i += stride) {
        int node = i >> 5;
        float sn = g_snorm[node];
        float2 v = *(const float2*)(feat + 2 * (size_t)i);
        g_FSa[i] = __float22half2_rn(make_float2(v.x * sn, v.y * sn));
        g_f0h[i] = __float22half2_rn(make_float2(ALPHA * v.x, ALPHA * v.y));
    }
}

// ---------------- APPNP propagation step (HALF-warp per node, pull/CSR) ----
// 16 lanes cover one 128B row (8B/lane); 2 independent nodes per warp.
// Two-level HADD2 tree: groups of 4 edges summed in fp16, fp32 accumulate.
// FO: 0 none, 1 -> rewrite g_f0h in place (phase-2 anchor), 2 -> write g_F2.
template<int FO>
__global__ __launch_bounds__(256) void appnp_step(const __half2* __restrict__ fs_in,
                                                  __half2* __restrict__ fs_out,
                                                  int n) {
    int node = blockIdx.x * 16 + (threadIdx.x >> 4);
    if (node >= n) return;
    int l16 = threadIdx.x & 15;           // lane's 8B chunk within the row
    const char* base = (const char*)fs_in + l16 * 8;

    int2 span = __ldg(&g_span[node]);
    int e = span.x;
    int end = span.x + span.y;

    float ax0 = 0.f, ax1 = 0.f, ax2 = 0.f, ax3 = 0.f;
    for (; e + 4 <= end; e += 4) {        // 4 independent row-reads in flight/half
        int o0 = __ldg(&g_csrc[e]);
        int o1 = __ldg(&g_csrc[e + 1]);
        int o2 = __ldg(&g_csrc[e + 2]);
        int o3 = __ldg(&g_csrc[e + 3]);
        uint2 v0 = __ldcg((const uint2*)(base + o0));
        uint2 v1 = __ldcg((const uint2*)(base + o1));
        uint2 v2 = __ldcg((const uint2*)(base + o2));
        uint2 v3 = __ldcg((const uint2*)(base + o3));
        __half2 x01 = __hadd2(u2h(v0.x), u2h(v1.x));   // level-1 fp16 adds
        __half2 x23 = __hadd2(u2h(v2.x), u2h(v3.x));
        __half2 y01 = __hadd2(u2h(v0.y), u2h(v1.y));
        __half2 y23 = __hadd2(u2h(v2.y), u2h(v3.y));
        __half2 xs = __hadd2(x01, x23);                // level-2
        __half2 ys = __hadd2(y01, y23);
        float2 fx = __half22float2(xs); ax0 += fx.x; ax1 += fx.y;
        float2 fy = __half22float2(ys); ax2 += fy.x; ax3 += fy.y;
    }
    for (; e + 2 <= end; e += 2) {        // pair tail, one HADD2 level
        int o0 = __ldg(&g_csrc[e]);
        int o1 = __ldg(&g_csrc[e + 1]);
        uint2 v0 = __ldcg((const uint2*)(base + o0));
        uint2 v1 = __ldcg((const uint2*)(base + o1));
        __half2 xs = __hadd2(u2h(v0.x), u2h(v1.x));
        __half2 ys = __hadd2(u2h(v0.y), u2h(v1.y));
        float2 fx = __half22float2(xs); ax0 += fx.x; ax1 += fx.y;
        float2 fy = __half22float2(ys); ax2 += fy.x; ax3 += fy.y;
    }
    if (e < end) {                        // single leftover edge
        int o = __ldg(&g_csrc[e]);
        uint2 v = __ldcg((const uint2*)(base + o));
        float2 fx = __half22float2(u2h(v.x)); ax0 += fx.x; ax1 += fx.y;
        float2 fy = __half22float2(u2h(v.y)); ax2 += fy.x; ax3 += fy.y;
    }

    float dn = g_dnorm[node];
    float sn = g_snorm[node];
    float w = 0.9f * dn;

    uint2 f0u = *((const uint2*)((const char*)g_f0h + (size_t)node * ROWB) + l16);
    float2 f0a = __half22float2(u2h(f0u.x));
    float2 f0b = __half22float2(u2h(f0u.y));

    float fx0 = w * ax0 + f0a.x;
    float fx1 = w * ax1 + f0a.y;
    float fx2 = w * ax2 + f0b.x;
    float fx3 = w * ax3 + f0b.y;

    __half2 h0 = __floats2half2_rn(fx0 * sn, fx1 * sn);
    __half2 h1 = __floats2half2_rn(fx2 * sn, fx3 * sn);
    uint2 wv;
    wv.x = *reinterpret_cast<unsigned int*>(&h0);
    wv.y = *reinterpret_cast<unsigned int*>(&h1);
    *((uint2*)((char*)fs_out + (size_t)node * ROWB) + l16) = wv;

    if (FO == 1) {                        // becomes phase-2 anchor: 0.1*f in fp16
        __half2 a0 = __floats2half2_rn(ALPHA * fx0, ALPHA * fx1);
        __half2 a1 = __floats2half2_rn(ALPHA * fx2, ALPHA * fx3);
        uint2 av;
        av.x = *reinterpret_cast<unsigned int*>(&a0);
        av.y = *reinterpret_cast<unsigned int*>(&a1);
        *((uint2*)((char*)g_f0h + (size_t)node * ROWB) + l16) = av;
    }
    if (FO == 2) {                        // final h (fp32) for the MLP
        ((float4*)(g_F2 + (size_t)node * DF))[l16] = make_float4(fx0, fx1, fx2, fx3);
    }
}

// ---------------- register-tiled SGEMM: C = [relu](A[MxK] @ W[KxNC] + b) ----
template<int K, int NC, bool RELU>
__global__ __launch_bounds__(256) void gemm_tiled(const float* __restrict__ A,
                                                  const float* __restrict__ W,
                                                  const float* __restrict__ bias,
                                                  float* __restrict__ C, int M) {
    constexpr int TX = NC / 4;       // 32 (NC=128) or 16 (NC=64)
    constexpr int TY = 256 / TX;     // 8 or 16
    constexpr int TM = 64 / TY;      // 8 or 4
    __shared__ float sAT[32][66];    // [k][row]
    __shared__ float sW[32][NC];

    int tid = threadIdx.x;
    int tx = tid % TX;
    int ty = tid / TX;
    int rowBase = blockIdx.x * 64;

    float acc[TM][4];
#pragma unroll
    for (int m = 0; m < TM; m++)
#pragma unroll
        for (int j = 0; j < 4; j++) acc[m][j] = 0.0f;

    for (int kk = 0; kk < K; kk += 32) {
        for (int i = tid; i < 64 * 32; i += 256) {
            int r = i >> 5, k = i & 31;
            int gr = rowBase + r;
            sAT[k][r] = (gr < M) ? A[(size_t)gr * K + kk + k] : 0.0f;
        }
        for (int i = tid; i < 32 * NC; i += 256) {
            int k = i / NC, c = i % NC;
            sW[k][c] = W[(size_t)(kk + k) * NC + c];
        }
        __syncthreads();
#pragma unroll
        for (int k = 0; k < 32; k++) {
            float4 w = *(const float4*)&sW[k][tx * 4];
            float a[TM];
#pragma unroll
            for (int m2 = 0; m2 < TM / 2; m2++) {
                float2 t = *(const float2*)&sAT[k][ty * TM + 2 * m2];
                a[2 * m2] = t.x; a[2 * m2 + 1] = t.y;
            }
#pragma unroll
            for (int m = 0; m < TM; m++) {
                acc[m][0] += a[m] * w.x;
                acc[m][1] += a[m] * w.y;
                acc[m][2] += a[m] * w.z;
                acc[m][3] += a[m] * w.w;
            }
        }
        __syncthreads();
    }

    float4 bv = *(const float4*)&bias[tx * 4];
#pragma unroll
    for (int m = 0; m < TM; m++) {
        int gr = rowBase + ty * TM + m;
        if (gr < M) {
            float4 v;
            v.x = acc[m][0] + bv.x;
            v.y = acc[m][1] + bv.y;
            v.z = acc[m][2] + bv.z;
            v.w = acc[m][3] + bv.w;
            if (RELU) {
                v.x = fmaxf(v.x, 0.0f); v.y = fmaxf(v.y, 0.0f);
                v.z = fmaxf(v.z, 0.0f); v.w = fmaxf(v.w, 0.0f);
            }
            *(float4*)&C[(size_t)gr * NC + tx * 4] = v;
        }
    }
}

// naive GEMM kept for the small head layer (K=64, NC=40)
template<int K, int NC, bool RELU>
__global__ __launch_bounds__(256) void gemm_small(const float* __restrict__ A,
                                                  const float* __restrict__ W,
                                                  const float* __restrict__ bias,
                                                  float* __restrict__ C, int M) {
    __shared__ float sA[64][33];
    __shared__ float sW[32][NC];
    const int CPT = NC / 4;
    float acc[CPT];
    int tid = threadIdx.x;
    int r  = tid >> 2;
    int cg = tid & 3;
    int row = blockIdx.x * 64 + r;
#pragma unroll
    for (int c = 0; c < CPT; c++) acc[c] = 0.0f;

    for (int kk = 0; kk < K; kk += 32) {
        for (int i = tid; i < 64 * 32; i += 256) {
            int rr = i >> 5, kx = i & 31;
            int grow = blockIdx.x * 64 + rr;
            sA[rr][kx] = (grow < M) ? A[(size_t)grow * K + kk + kx] : 0.0f;
        }
        for (int i = tid; i < 32 * NC; i += 256) {
            int kx = i / NC, cx = i % NC;
            sW[kx][cx] = W[(size_t)(kk + kx) * NC + cx];
        }
        __syncthreads();
#pragma unroll
        for (int k = 0; k < 32; k++) {
            float a = sA[r][k];
#pragma unroll
            for (int c = 0; c < CPT; c++) acc[c] += a * sW[k][c * 4 + cg];
        }
        __syncthreads();
    }

    if (row < M) {
#pragma unroll
        for (int c = 0; c < CPT; c++) {
            float v = acc[c] + bias[c * 4 + cg];
            if (RELU) v = fmaxf(v, 0.0f);
            C[(size_t)row * NC + c * 4 + cg] = v;
        }
    }
}

// ---------------- launch ----------------------------------------------------
extern "C" void kernel_launch(void* const* d_in, const int* in_sizes, int n_in,
                              void* d_out, int out_size) {
    const float* feat = (const float*)d_in[0];
    const int*   src  = (const int*)  d_in[1];
    const int*   dst  = (const int*)  d_in[2];
    const float* W1   = (const float*)d_in[3];
    const float* b1   = (const float*)d_in[4];
    const float* W2   = (const float*)d_in[5];
    const float* b2   = (const float*)d_in[6];
    const float* Wh1  = (const float*)d_in[7];
    const float* bh1  = (const float*)d_in[8];
    const float* Wh2  = (const float*)d_in[9];
    const float* bh2  = (const float*)d_in[10];
    float* out = (float*)d_out;

    int n = in_sizes[0] / DF;
    int e = in_sizes[1];

    void *pF2, *pFa, *pFb, *pT1, *pT2;
    cudaGetSymbolAddress(&pF2, g_F2);
    cudaGetSymbolAddress(&pFa, g_FSa);
    cudaGetSymbolAddress(&pFb, g_FSb);
    cudaGetSymbolAddress(&pT1, g_t1);
    cudaGetSymbolAddress(&pT2, g_t2);
    float*   F2  = (float*)pF2;
    __half2* FSa = (__half2*)pFa;
    __half2* FSb = (__half2*)pFb;
    float*   T1  = (float*)pT1;
    float*   T2  = (float*)pT2;

    // exact one co-resident wave for finalize's internal grid barrier
    int dev = 0, sms = 0, occ = 0;
    cudaGetDevice(&dev);
    cudaDeviceGetAttribute(&sms, cudaDevAttrMultiProcessorCount, dev);
    cudaOccupancyMaxActiveBlocksPerMultiprocessor(&occ, finalize_kernel, 256, 0);
    if (occ < 1) occ = 1;
    int fblocks = sms * occ;

    // --- preprocessing: exactly 3 launches (4th launch = appnp_step #0) ---
    zero_kernel    <<<(n + 255) / 256, 256>>>(n);
    deg_kernel     <<<(e + 255) / 256, 256>>>(src, dst, e);
    finalize_kernel<<<fblocks, 256>>>(src, dst, feat, n, e);

    // --- 20 propagation steps (2 APPNP phases of K=10) ---
    int step_blocks = (n + 15) / 16;  // 16 half-warps (nodes) per 256-thread block
    __half2* fin = FSa; __half2* fout = FSb;
    for (int s = 0; s < 20; s++) {
        if      (s == 9)  appnp_step<1><<<step_blocks, 256>>>(fin, fout, n);
        else if (s == 19) appnp_step<2><<<step_blocks, 256>>>(fin, fout, n);
        else              appnp_step<0><<<step_blocks, 256>>>(fin, fout, n);
        __half2* t = fin; fin = fout; fout = t;
    }

    // --- MLP trunk + head (fp32 SGEMMs) ---
    float* h_last = out + (size_t)n * CCH;   // d_out = [out (N*40)] [h_last (N*128)]
    int gb = (n + 63) / 64;
    gemm_tiled<DF,  HH,  true ><<<gb, 256>>>(F2,     W1,  b1,  T1,     n);
    gemm_tiled<HH,  HH,  false><<<gb, 256>>>(T1,     W2,  b2,  h_last, n);
    gemm_tiled<HH,  HHF, true ><<<gb, 256>>>(h_last, Wh1, bh1, T2,     n);
    gemm_small<HHF, CCH, false><<<gb, 256>>>(T2,     Wh2, bh2, out,    n);
}

// round 11
// speedup vs baseline: 2.8571x; 1.0821x over previous
#include <cuda_runtime.h>
#include <cuda_fp16.h>
#include <math.h>

// ---------------- static problem sizes (from reference setup_inputs) -------
#define NMAX 100352      // >= N=100000
#define EMAX 1000448     // >= E=1000000
#define DF   64          // input feature dim
#define DF2  32          // half2 elements per row
#define ROWB 128         // bytes per fp16 feature row
#define HH   128         // hidden
#define HHF  64          // H/2
#define CCH  40          // classes
#define ALPHA 0.1f

// ---------------- device scratch (no allocations allowed) ------------------
__device__ float   g_F2 [NMAX * DF];    // phase-2 result (h) -> MLP input (fp32)
__device__ __half2 g_FSa[NMAX * DF2];   // scaled feature ping (fp16)
__device__ __half2 g_FSb[NMAX * DF2];   // scaled feature pong (fp16)
__device__ __half2 g_f0h[NMAX * DF2];   // alpha-premultiplied f0 (fp16)
__device__ float   g_t1 [NMAX * HH];    // MLP intermediate
__device__ float   g_t2 [NMAX * HHF];   // MLP intermediate
__device__ int     g_din [NMAX];
__device__ int     g_dout[NMAX];
__device__ int     g_cur [NMAX];
__device__ int     g_rowptr[NMAX];
__device__ int2    g_span[NMAX];        // (edge offset, degree) packed
__device__ int     g_csrc[EMAX];        // BYTE offsets (src*128), not indices
__device__ float   g_snorm[NMAX];
__device__ float   g_dnorm[NMAX];
__device__ int     g_total;
__device__ int          g_count;        // grid-barrier arrive counter
__device__ volatile int g_sense;        // grid-barrier phase

__device__ __forceinline__ __half2 u2h(unsigned int u) {
    return *reinterpret_cast<__half2*>(&u);
}

// ---------------- launch 1: zero --------------------------------------------
__global__ void zero_kernel(int n) {
    int i = blockIdx.x * blockDim.x + threadIdx.x;
    if (i < n) { g_din[i] = 0; g_dout[i] = 0; g_cur[i] = 0; }
    if (i == 0) { g_total = 0; g_count = 0; g_sense = 0; }
}

// ---------------- launch 2: degree histogram --------------------------------
__global__ void deg_kernel(const int* __restrict__ src, const int* __restrict__ dst, int e) {
    int i = blockIdx.x * blockDim.x + threadIdx.x;
    if (i < e) {
        atomicAdd(&g_dout[src[i]], 1);
        atomicAdd(&g_din [dst[i]], 1);
    }
}

// ---------------- grid-wide software barrier (all blocks co-resident) -------
__device__ __forceinline__ void grid_sync(int phase) {
    __syncthreads();
    if (threadIdx.x == 0) {
        __threadfence();
        if (atomicAdd(&g_count, 1) == (int)gridDim.x - 1) {
            g_count = 0;
            __threadfence();
            g_sense = phase;       // release
        } else {
            while (g_sense < phase) __nanosleep(40);
            __threadfence();       // acquire
        }
    }
    __syncthreads();
}

// ---------------- launch 3: fused finalize ----------------------------------
__global__ __launch_bounds__(256) void finalize_kernel(const int* __restrict__ src,
                                                       const int* __restrict__ dst,
                                                       const float* __restrict__ feat,
                                                       int n, int e) {
    int gtid = blockIdx.x * blockDim.x + threadIdx.x;
    int stride = gridDim.x * blockDim.x;
    int lane = threadIdx.x & 31;

    for (int base = 0; base < n; base += stride) {
        int i = base + gtid;
        int d = 0;
        if (i < n) {
            int o = g_dout[i];
            d = g_din[i];
            g_snorm[i] = (o > 0) ? rsqrtf((float)o) : 0.0f;
            g_dnorm[i] = (d > 0) ? rsqrtf((float)d) : 0.0f;
        }
        int x = d;
#pragma unroll
        for (int off = 1; off < 32; off <<= 1) {
            int y = __shfl_up_sync(0xffffffffu, x, off);
            if (lane >= off) x += y;
        }
        int tot = __shfl_sync(0xffffffffu, x, 31);
        int bofs = 0;
        if (lane == 31 && tot > 0) bofs = atomicAdd(&g_total, tot);
        bofs = __shfl_sync(0xffffffffu, bofs, 31);
        if (i < n) {
            int o = bofs + x - d;
            g_rowptr[i] = o;
            g_span[i] = make_int2(o, d);
        }
    }

    grid_sync(1);

    for (int i = gtid; i < e; i += stride) {
        int dd = dst[i];
        int p = g_rowptr[dd] + atomicAdd(&g_cur[dd], 1);
        g_csrc[p] = src[i] << 7;           // byte offset into 128B-row buffer
    }

    int n32 = n * DF2;
    for (int i = gtid; i < n32; i += stride) {
        int node = i >> 5;
        float sn = g_snorm[node];
        float2 v = *(const float2*)(feat + 2 * (size_t)i);
        g_FSa[i] = __float22half2_rn(make_float2(v.x * sn, v.y * sn));
        g_f0h[i] = __float22half2_rn(make_float2(ALPHA * v.x, ALPHA * v.y));
    }
}

// ---------------- APPNP propagation step (QUARTER-warp per node) ------------
// 8 lanes x 16B (uint4) cover one 128B row; 4 independent nodes per warp
// (4 independent load chains). Two-level HADD2 tree on 4-edge groups.
// FO: 0 none, 1 -> rewrite g_f0h in place (phase-2 anchor), 2 -> write g_F2.
template<int FO>
__global__ __launch_bounds__(256) void appnp_step(const __half2* __restrict__ fs_in,
                                                  __half2* __restrict__ fs_out,
                                                  int n) {
    int node = blockIdx.x * 32 + (threadIdx.x >> 3);
    if (node >= n) return;
    int l8 = threadIdx.x & 7;             // lane's 16B chunk within the row
    const char* base = (const char*)fs_in + l8 * 16;

    int2 span = __ldg(&g_span[node]);
    int e = span.x;
    int end = span.x + span.y;

    float ax0 = 0.f, ax1 = 0.f, ax2 = 0.f, ax3 = 0.f;
    float ax4 = 0.f, ax5 = 0.f, ax6 = 0.f, ax7 = 0.f;
    for (; e + 4 <= end; e += 4) {        // 4 independent 128B row-reads in flight
        int o0 = __ldg(&g_csrc[e]);
        int o1 = __ldg(&g_csrc[e + 1]);
        int o2 = __ldg(&g_csrc[e + 2]);
        int o3 = __ldg(&g_csrc[e + 3]);
        uint4 v0 = __ldcg((const uint4*)(base + o0));
        uint4 v1 = __ldcg((const uint4*)(base + o1));
        uint4 v2 = __ldcg((const uint4*)(base + o2));
        uint4 v3 = __ldcg((const uint4*)(base + o3));
        __half2 sx = __hadd2(__hadd2(u2h(v0.x), u2h(v1.x)), __hadd2(u2h(v2.x), u2h(v3.x)));
        __half2 sy = __hadd2(__hadd2(u2h(v0.y), u2h(v1.y)), __hadd2(u2h(v2.y), u2h(v3.y)));
        __half2 sz = __hadd2(__hadd2(u2h(v0.z), u2h(v1.z)), __hadd2(u2h(v2.z), u2h(v3.z)));
        __half2 sw = __hadd2(__hadd2(u2h(v0.w), u2h(v1.w)), __hadd2(u2h(v2.w), u2h(v3.w)));
        float2 f;
        f = __half22float2(sx); ax0 += f.x; ax1 += f.y;
        f = __half22float2(sy); ax2 += f.x; ax3 += f.y;
        f = __half22float2(sz); ax4 += f.x; ax5 += f.y;
        f = __half22float2(sw); ax6 += f.x; ax7 += f.y;
    }
    for (; e + 2 <= end; e += 2) {        // pair tail, one HADD2 level
        int o0 = __ldg(&g_csrc[e]);
        int o1 = __ldg(&g_csrc[e + 1]);
        uint4 v0 = __ldcg((const uint4*)(base + o0));
        uint4 v1 = __ldcg((const uint4*)(base + o1));
        __half2 sx = __hadd2(u2h(v0.x), u2h(v1.x));
        __half2 sy = __hadd2(u2h(v0.y), u2h(v1.y));
        __half2 sz = __hadd2(u2h(v0.z), u2h(v1.z));
        __half2 sw = __hadd2(u2h(v0.w), u2h(v1.w));
        float2 f;
        f = __half22float2(sx); ax0 += f.x; ax1 += f.y;
        f = __half22float2(sy); ax2 += f.x; ax3 += f.y;
        f = __half22float2(sz); ax4 += f.x; ax5 += f.y;
        f = __half22float2(sw); ax6 += f.x; ax7 += f.y;
    }
    if (e < end) {                        // single leftover edge
        int o = __ldg(&g_csrc[e]);
        uint4 v = __ldcg((const uint4*)(base + o));
        float2 f;
        f = __half22float2(u2h(v.x)); ax0 += f.x; ax1 += f.y;
        f = __half22float2(u2h(v.y)); ax2 += f.x; ax3 += f.y;
        f = __half22float2(u2h(v.z)); ax4 += f.x; ax5 += f.y;
        f = __half22float2(u2h(v.w)); ax6 += f.x; ax7 += f.y;
    }

    float dn = g_dnorm[node];
    float sn = g_snorm[node];
    float w = 0.9f * dn;

    uint4 f0u = ((const uint4*)((const char*)g_f0h + (size_t)node * ROWB))[l8];
    float2 f0a = __half22float2(u2h(f0u.x));
    float2 f0b = __half22float2(u2h(f0u.y));
    float2 f0c = __half22float2(u2h(f0u.z));
    float2 f0d = __half22float2(u2h(f0u.w));

    float fx0 = w * ax0 + f0a.x;
    float fx1 = w * ax1 + f0a.y;
    float fx2 = w * ax2 + f0b.x;
    float fx3 = w * ax3 + f0b.y;
    float fx4 = w * ax4 + f0c.x;
    float fx5 = w * ax5 + f0c.y;
    float fx6 = w * ax6 + f0d.x;
    float fx7 = w * ax7 + f0d.y;

    __half2 h0 = __floats2half2_rn(fx0 * sn, fx1 * sn);
    __half2 h1 = __floats2half2_rn(fx2 * sn, fx3 * sn);
    __half2 h2 = __floats2half2_rn(fx4 * sn, fx5 * sn);
    __half2 h3 = __floats2half2_rn(fx6 * sn, fx7 * sn);
    uint4 wv;
    wv.x = *reinterpret_cast<unsigned int*>(&h0);
    wv.y = *reinterpret_cast<unsigned int*>(&h1);
    wv.z = *reinterpret_cast<unsigned int*>(&h2);
    wv.w = *reinterpret_cast<unsigned int*>(&h3);
    ((uint4*)((char*)fs_out + (size_t)node * ROWB))[l8] = wv;

    if (FO == 1) {                        // becomes phase-2 anchor: 0.1*f in fp16
        __half2 a0 = __floats2half2_rn(ALPHA * fx0, ALPHA * fx1);
        __half2 a1 = __floats2half2_rn(ALPHA * fx2, ALPHA * fx3);
        __half2 a2 = __floats2half2_rn(ALPHA * fx4, ALPHA * fx5);
        __half2 a3 = __floats2half2_rn(ALPHA * fx6, ALPHA * fx7);
        uint4 av;
        av.x = *reinterpret_cast<unsigned int*>(&a0);
        av.y = *reinterpret_cast<unsigned int*>(&a1);
        av.z = *reinterpret_cast<unsigned int*>(&a2);
        av.w = *reinterpret_cast<unsigned int*>(&a3);
        ((uint4*)((char*)g_f0h + (size_t)node * ROWB))[l8] = av;
    }
    if (FO == 2) {                        // final h (fp32) for the MLP
        ((float4*)(g_F2 + (size_t)node * DF))[2 * l8]     = make_float4(fx0, fx1, fx2, fx3);
        ((float4*)(g_F2 + (size_t)node * DF))[2 * l8 + 1] = make_float4(fx4, fx5, fx6, fx7);
    }
}

// ---------------- register-tiled SGEMM: C = [relu](A[MxK] @ W[KxNC] + b) ----
template<int K, int NC, bool RELU>
__global__ __launch_bounds__(256) void gemm_tiled(const float* __restrict__ A,
                                                  const float* __restrict__ W,
                                                  const float* __restrict__ bias,
                                                  float* __restrict__ C, int M) {
    constexpr int TX = NC / 4;       // 32 (NC=128) or 16 (NC=64)
    constexpr int TY = 256 / TX;     // 8 or 16
    constexpr int TM = 64 / TY;      // 8 or 4
    __shared__ float sAT[32][66];    // [k][row]
    __shared__ float sW[32][NC];

    int tid = threadIdx.x;
    int tx = tid % TX;
    int ty = tid / TX;
    int rowBase = blockIdx.x * 64;

    float acc[TM][4];
#pragma unroll
    for (int m = 0; m < TM; m++)
#pragma unroll
        for (int j = 0; j < 4; j++) acc[m][j] = 0.0f;

    for (int kk = 0; kk < K; kk += 32) {
        for (int i = tid; i < 64 * 32; i += 256) {
            int r = i >> 5, k = i & 31;
            int gr = rowBase + r;
            sAT[k][r] = (gr < M) ? A[(size_t)gr * K + kk + k] : 0.0f;
        }
        for (int i = tid; i < 32 * NC; i += 256) {
            int k = i / NC, c = i % NC;
            sW[k][c] = W[(size_t)(kk + k) * NC + c];
        }
        __syncthreads();
#pragma unroll
        for (int k = 0; k < 32; k++) {
            float4 w = *(const float4*)&sW[k][tx * 4];
            float a[TM];
#pragma unroll
            for (int m2 = 0; m2 < TM / 2; m2++) {
                float2 t = *(const float2*)&sAT[k][ty * TM + 2 * m2];
                a[2 * m2] = t.x; a[2 * m2 + 1] = t.y;
            }
#pragma unroll
            for (int m = 0; m < TM; m++) {
                acc[m][0] += a[m] * w.x;
                acc[m][1] += a[m] * w.y;
                acc[m][2] += a[m] * w.z;
                acc[m][3] += a[m] * w.w;
            }
        }
        __syncthreads();
    }

    float4 bv = *(const float4*)&bias[tx * 4];
#pragma unroll
    for (int m = 0; m < TM; m++) {
        int gr = rowBase + ty * TM + m;
        if (gr < M) {
            float4 v;
            v.x = acc[m][0] + bv.x;
            v.y = acc[m][1] + bv.y;
            v.z = acc[m][2] + bv.z;
            v.w = acc[m][3] + bv.w;
            if (RELU) {
                v.x = fmaxf(v.x, 0.0f); v.y = fmaxf(v.y, 0.0f);
                v.z = fmaxf(v.z, 0.0f); v.w = fmaxf(v.w, 0.0f);
            }
            *(float4*)&C[(size_t)gr * NC + tx * 4] = v;
        }
    }
}

// naive GEMM kept for the small head layer (K=64, NC=40)
template<int K, int NC, bool RELU>
__global__ __launch_bounds__(256) void gemm_small(const float* __restrict__ A,
                                                  const float* __restrict__ W,
                                                  const float* __restrict__ bias,
                                                  float* __restrict__ C, int M) {
    __shared__ float sA[64][33];
    __shared__ float sW[32][NC];
    const int CPT = NC / 4;
    float acc[CPT];
    int tid = threadIdx.x;
    int r  = tid >> 2;
    int cg = tid & 3;
    int row = blockIdx.x * 64 + r;
#pragma unroll
    for (int c = 0; c < CPT; c++) acc[c] = 0.0f;

    for (int kk = 0; kk < K; kk += 32) {
        for (int i = tid; i < 64 * 32; i += 256) {
            int rr = i >> 5, kx = i & 31;
            int grow = blockIdx.x * 64 + rr;
            sA[rr][kx] = (grow < M) ? A[(size_t)grow * K + kk + kx] : 0.0f;
        }
        for (int i = tid; i < 32 * NC; i += 256) {
            int kx = i / NC, cx = i % NC;
            sW[kx][cx] = W[(size_t)(kk + kx) * NC + cx];
        }
        __syncthreads();
#pragma unroll
        for (int k = 0; k < 32; k++) {
            float a = sA[r][k];
#pragma unroll
            for (int c = 0; c < CPT; c++) acc[c] += a * sW[k][c * 4 + cg];
        }
        __syncthreads();
    }

    if (row < M) {
#pragma unroll
        for (int c = 0; c < CPT; c++) {
            float v = acc[c] + bias[c * 4 + cg];
            if (RELU) v = fmaxf(v, 0.0f);
            C[(size_t)row * NC + c * 4 + cg] = v;
        }
    }
}

// ---------------- launch ----------------------------------------------------
extern "C" void kernel_launch(void* const* d_in, const int* in_sizes, int n_in,
                              void* d_out, int out_size) {
    const float* feat = (const float*)d_in[0];
    const int*   src  = (const int*)  d_in[1];
    const int*   dst  = (const int*)  d_in[2];
    const float* W1   = (const float*)d_in[3];
    const float* b1   = (const float*)d_in[4];
    const float* W2   = (const float*)d_in[5];
    const float* b2   = (const float*)d_in[6];
    const float* Wh1  = (const float*)d_in[7];
    const float* bh1  = (const float*)d_in[8];
    const float* Wh2  = (const float*)d_in[9];
    const float* bh2  = (const float*)d_in[10];
    float* out = (float*)d_out;

    int n = in_sizes[0] / DF;
    int e = in_sizes[1];

    void *pF2, *pFa, *pFb, *pT1, *pT2;
    cudaGetSymbolAddress(&pF2, g_F2);
    cudaGetSymbolAddress(&pFa, g_FSa);
    cudaGetSymbolAddress(&pFb, g_FSb);
    cudaGetSymbolAddress(&pT1, g_t1);
    cudaGetSymbolAddress(&pT2, g_t2);
    float*   F2  = (float*)pF2;
    __half2* FSa = (__half2*)pFa;
    __half2* FSb = (__half2*)pFb;
    float*   T1  = (float*)pT1;
    float*   T2  = (float*)pT2;

    // exact one co-resident wave for finalize's internal grid barrier
    int dev = 0, sms = 0, occ = 0;
    cudaGetDevice(&dev);
    cudaDeviceGetAttribute(&sms, cudaDevAttrMultiProcessorCount, dev);
    cudaOccupancyMaxActiveBlocksPerMultiprocessor(&occ, finalize_kernel, 256, 0);
    if (occ < 1) occ = 1;
    int fblocks = sms * occ;

    // --- preprocessing: exactly 3 launches (4th launch = appnp_step #0) ---
    zero_kernel    <<<(n + 255) / 256, 256>>>(n);
    deg_kernel     <<<(e + 255) / 256, 256>>>(src, dst, e);
    finalize_kernel<<<fblocks, 256>>>(src, dst, feat, n, e);

    // --- 20 propagation steps (2 APPNP phases of K=10) ---
    int step_blocks = (n + 31) / 32;  // 32 quarter-warps (nodes) per 256-thread block
    __half2* fin = FSa; __half2* fout = FSb;
    for (int s = 0; s < 20; s++) {
        if      (s == 9)  appnp_step<1><<<step_blocks, 256>>>(fin, fout, n);
        else if (s == 19) appnp_step<2><<<step_blocks, 256>>>(fin, fout, n);
        else              appnp_step<0><<<step_blocks, 256>>>(fin, fout, n);
        __half2* t = fin; fin = fout; fout = t;
    }

    // --- MLP trunk + head (fp32 SGEMMs) ---
    float* h_last = out + (size_t)n * CCH;   // d_out = [out (N*40)] [h_last (N*128)]
    int gb = (n + 63) / 64;
    gemm_tiled<DF,  HH,  true ><<<gb, 256>>>(F2,     W1,  b1,  T1,     n);
    gemm_tiled<HH,  HH,  false><<<gb, 256>>>(T1,     W2,  b2,  h_last, n);
    gemm_tiled<HH,  HHF, true ><<<gb, 256>>>(h_last, Wh1, bh1, T2,     n);
    gemm_small<HHF, CCH, false><<<gb, 256>>>(T2,     Wh2, bh2, out,    n);
}

// round 12
// speedup vs baseline: 2.9287x; 1.0251x over previous
#include <cuda_runtime.h>
#include <cuda_fp16.h>
#include <math.h>

// ---------------- static problem sizes (from reference setup_inputs) -------
#define NMAX 100352      // >= N=100000
#define EMAX 1000448     // >= E=1000000
#define DF   64          // input feature dim
#define DF2  32          // half2 elements per row
#define ROWB 128         // bytes per fp16 feature row
#define HH   128         // hidden
#define HHF  64          // H/2
#define CCH  40          // classes
#define ALPHA 0.1f

// ---------------- device scratch (no allocations allowed) ------------------
__device__ float   g_F2 [NMAX * DF];    // phase-2 result (h) -> MLP input (fp32)
__device__ __half2 g_FSa[NMAX * DF2];   // scaled feature ping (fp16)
__device__ __half2 g_FSb[NMAX * DF2];   // scaled feature pong (fp16)
__device__ __half2 g_f0h[NMAX * DF2];   // alpha-premultiplied f0 (fp16)
__device__ float   g_t1 [NMAX * HH];    // MLP intermediate
__device__ float   g_t2 [NMAX * HHF];   // MLP intermediate
__device__ int     g_din [NMAX];
__device__ int     g_dout[NMAX];
__device__ int     g_cur [NMAX];
__device__ int     g_rowptr[NMAX];
__device__ int2    g_span[NMAX];        // (edge offset, degree) packed
__device__ int     g_csrc[EMAX];        // BYTE offsets (src*128), not indices
__device__ float   g_snorm[NMAX];
__device__ float   g_dnorm[NMAX];
__device__ int     g_total;
__device__ int          g_count;        // grid-barrier arrive counter
__device__ volatile int g_sense;        // grid-barrier phase

__device__ __forceinline__ __half2 u2h(unsigned int u) {
    return *reinterpret_cast<__half2*>(&u);
}

// ---------------- launch 1: zero --------------------------------------------
__global__ void zero_kernel(int n) {
    int i = blockIdx.x * blockDim.x + threadIdx.x;
    if (i < n) { g_din[i] = 0; g_dout[i] = 0; g_cur[i] = 0; }
    if (i == 0) { g_total = 0; g_count = 0; g_sense = 0; }
}

// ---------------- launch 2: degree histogram --------------------------------
__global__ void deg_kernel(const int* __restrict__ src, const int* __restrict__ dst, int e) {
    int i = blockIdx.x * blockDim.x + threadIdx.x;
    if (i < e) {
        atomicAdd(&g_dout[src[i]], 1);
        atomicAdd(&g_din [dst[i]], 1);
    }
}

// ---------------- grid-wide software barrier (all blocks co-resident) -------
__device__ __forceinline__ void grid_sync(int phase) {
    __syncthreads();
    if (threadIdx.x == 0) {
        __threadfence();
        if (atomicAdd(&g_count, 1) == (int)gridDim.x - 1) {
            g_count = 0;
            __threadfence();
            g_sense = phase;       // release
        } else {
            while (g_sense < phase) __nanosleep(40);
            __threadfence();       // acquire
        }
    }
    __syncthreads();
}

// ---------------- launch 3: fused finalize ----------------------------------
__global__ __launch_bounds__(256) void finalize_kernel(const int* __restrict__ src,
                                                       const int* __restrict__ dst,
                                                       const float* __restrict__ feat,
                                                       int n, int e) {
    int gtid = blockIdx.x * blockDim.x + threadIdx.x;
    int stride = gridDim.x * blockDim.x;
    int lane = threadIdx.x & 31;

    for (int base = 0; base < n; base += stride) {
        int i = base + gtid;
        int d = 0;
        if (i < n) {
            int o = g_dout[i];
            d = g_din[i];
            g_snorm[i] = (o > 0) ? rsqrtf((float)o) : 0.0f;
            g_dnorm[i] = (d > 0) ? rsqrtf((float)d) : 0.0f;
        }
        int x = d;
#pragma unroll
        for (int off = 1; off < 32; off <<= 1) {
            int y = __shfl_up_sync(0xffffffffu, x, off);
            if (lane >= off) x += y;
        }
        int tot = __shfl_sync(0xffffffffu, x, 31);
        int bofs = 0;
        if (lane == 31 && tot > 0) bofs = atomicAdd(&g_total, tot);
        bofs = __shfl_sync(0xffffffffu, bofs, 31);
        if (i < n) {
            int o = bofs + x - d;
            g_rowptr[i] = o;
            g_span[i] = make_int2(o, d);
        }
    }

    grid_sync(1);

    for (int i = gtid; i < e; i += stride) {
        int dd = dst[i];
        int p = g_rowptr[dd] + atomicAdd(&g_cur[dd], 1);
        g_csrc[p] = src[i] << 7;           // byte offset into 128B-row buffer
    }

    int n32 = n * DF2;
    for (int i = gtid; i < n32; i += stride) {
        int node = i >> 5;
        float sn = g_snorm[node];
        float2 v = *(const float2*)(feat + 2 * (size_t)i);
        g_FSa[i] = __float22half2_rn(make_float2(v.x * sn, v.y * sn));
        g_f0h[i] = __float22half2_rn(make_float2(ALPHA * v.x, ALPHA * v.y));
    }
}

// ---------------- APPNP propagation step (QUARTER-warp per node) ------------
// 8 lanes x 16B (uint4) cover one 128B row; 4 independent nodes per warp.
// Offset loads are SOFTWARE-PIPELINED one 4-edge group ahead so row loads
// never wait on an offset round-trip. Two-level HADD2 tree on 4-edge groups.
// FO: 0 none, 1 -> rewrite g_f0h in place (phase-2 anchor), 2 -> write g_F2.
template<int FO>
__global__ __launch_bounds__(256) void appnp_step(const __half2* __restrict__ fs_in,
                                                  __half2* __restrict__ fs_out,
                                                  int n) {
    int node = blockIdx.x * 32 + (threadIdx.x >> 3);
    if (node >= n) return;
    int l8 = threadIdx.x & 7;             // lane's 16B chunk within the row
    const char* base = (const char*)fs_in + l8 * 16;

    int2 span = __ldg(&g_span[node]);
    int e = span.x;
    int end = span.x + span.y;

    float ax0 = 0.f, ax1 = 0.f, ax2 = 0.f, ax3 = 0.f;
    float ax4 = 0.f, ax5 = 0.f, ax6 = 0.f, ax7 = 0.f;

    int o0, o1, o2, o3;
    if (e + 4 <= end) {                   // prologue: offsets for group 0
        o0 = __ldg(&g_csrc[e]);
        o1 = __ldg(&g_csrc[e + 1]);
        o2 = __ldg(&g_csrc[e + 2]);
        o3 = __ldg(&g_csrc[e + 3]);
    }
    for (; e + 8 <= end; e += 4) {        // steady state: prefetch next group
        int no0 = __ldg(&g_csrc[e + 4]);
        int no1 = __ldg(&g_csrc[e + 5]);
        int no2 = __ldg(&g_csrc[e + 6]);
        int no3 = __ldg(&g_csrc[e + 7]);
        uint4 v0 = __ldcg((const uint4*)(base + o0));
        uint4 v1 = __ldcg((const uint4*)(base + o1));
        uint4 v2 = __ldcg((const uint4*)(base + o2));
        uint4 v3 = __ldcg((const uint4*)(base + o3));
        __half2 sx = __hadd2(__hadd2(u2h(v0.x), u2h(v1.x)), __hadd2(u2h(v2.x), u2h(v3.x)));
        __half2 sy = __hadd2(__hadd2(u2h(v0.y), u2h(v1.y)), __hadd2(u2h(v2.y), u2h(v3.y)));
        __half2 sz = __hadd2(__hadd2(u2h(v0.z), u2h(v1.z)), __hadd2(u2h(v2.z), u2h(v3.z)));
        __half2 sw = __hadd2(__hadd2(u2h(v0.w), u2h(v1.w)), __hadd2(u2h(v2.w), u2h(v3.w)));
        float2 f;
        f = __half22float2(sx); ax0 += f.x; ax1 += f.y;
        f = __half22float2(sy); ax2 += f.x; ax3 += f.y;
        f = __half22float2(sz); ax4 += f.x; ax5 += f.y;
        f = __half22float2(sw); ax6 += f.x; ax7 += f.y;
        o0 = no0; o1 = no1; o2 = no2; o3 = no3;
    }
    if (e + 4 <= end) {                   // last full group (offsets in hand)
        uint4 v0 = __ldcg((const uint4*)(base + o0));
        uint4 v1 = __ldcg((const uint4*)(base + o1));
        uint4 v2 = __ldcg((const uint4*)(base + o2));
        uint4 v3 = __ldcg((const uint4*)(base + o3));
        __half2 sx = __hadd2(__hadd2(u2h(v0.x), u2h(v1.x)), __hadd2(u2h(v2.x), u2h(v3.x)));
        __half2 sy = __hadd2(__hadd2(u2h(v0.y), u2h(v1.y)), __hadd2(u2h(v2.y), u2h(v3.y)));
        __half2 sz = __hadd2(__hadd2(u2h(v0.z), u2h(v1.z)), __hadd2(u2h(v2.z), u2h(v3.z)));
        __half2 sw = __hadd2(__hadd2(u2h(v0.w), u2h(v1.w)), __hadd2(u2h(v2.w), u2h(v3.w)));
        float2 f;
        f = __half22float2(sx); ax0 += f.x; ax1 += f.y;
        f = __half22float2(sy); ax2 += f.x; ax3 += f.y;
        f = __half22float2(sz); ax4 += f.x; ax5 += f.y;
        f = __half22float2(sw); ax6 += f.x; ax7 += f.y;
        e += 4;
    }
    for (; e + 2 <= end; e += 2) {        // pair tail, one HADD2 level
        int p0 = __ldg(&g_csrc[e]);
        int p1 = __ldg(&g_csrc[e + 1]);
        uint4 v0 = __ldcg((const uint4*)(base + p0));
        uint4 v1 = __ldcg((const uint4*)(base + p1));
        __half2 sx = __hadd2(u2h(v0.x), u2h(v1.x));
        __half2 sy = __hadd2(u2h(v0.y), u2h(v1.y));
        __half2 sz = __hadd2(u2h(v0.z), u2h(v1.z));
        __half2 sw = __hadd2(u2h(v0.w), u2h(v1.w));
        float2 f;
        f = __half22float2(sx); ax0 += f.x; ax1 += f.y;
        f = __half22float2(sy); ax2 += f.x; ax3 += f.y;
        f = __half22float2(sz); ax4 += f.x; ax5 += f.y;
        f = __half22float2(sw); ax6 += f.x; ax7 += f.y;
    }
    if (e < end) {                        // single leftover edge
        int p = __ldg(&g_csrc[e]);
        uint4 v = __ldcg((const uint4*)(base + p));
        float2 f;
        f = __half22float2(u2h(v.x)); ax0 += f.x; ax1 += f.y;
        f = __half22float2(u2h(v.y)); ax2 += f.x; ax3 += f.y;
        f = __half22float2(u2h(v.z)); ax4 += f.x; ax5 += f.y;
        f = __half22float2(u2h(v.w)); ax6 += f.x; ax7 += f.y;
    }

    float dn = g_dnorm[node];
    float sn = g_snorm[node];
    float w = 0.9f * dn;

    uint4 f0u = ((const uint4*)((const char*)g_f0h + (size_t)node * ROWB))[l8];
    float2 f0a = __half22float2(u2h(f0u.x));
    float2 f0b = __half22float2(u2h(f0u.y));
    float2 f0c = __half22float2(u2h(f0u.z));
    float2 f0d = __half22float2(u2h(f0u.w));

    float fx0 = w * ax0 + f0a.x;
    float fx1 = w * ax1 + f0a.y;
    float fx2 = w * ax2 + f0b.x;
    float fx3 = w * ax3 + f0b.y;
    float fx4 = w * ax4 + f0c.x;
    float fx5 = w * ax5 + f0c.y;
    float fx6 = w * ax6 + f0d.x;
    float fx7 = w * ax7 + f0d.y;

    __half2 h0 = __floats2half2_rn(fx0 * sn, fx1 * sn);
    __half2 h1 = __floats2half2_rn(fx2 * sn, fx3 * sn);
    __half2 h2 = __floats2half2_rn(fx4 * sn, fx5 * sn);
    __half2 h3 = __floats2half2_rn(fx6 * sn, fx7 * sn);
    uint4 wv;
    wv.x = *reinterpret_cast<unsigned int*>(&h0);
    wv.y = *reinterpret_cast<unsigned int*>(&h1);
    wv.z = *reinterpret_cast<unsigned int*>(&h2);
    wv.w = *reinterpret_cast<unsigned int*>(&h3);
    ((uint4*)((char*)fs_out + (size_t)node * ROWB))[l8] = wv;

    if (FO == 1) {                        // becomes phase-2 anchor: 0.1*f in fp16
        __half2 a0 = __floats2half2_rn(ALPHA * fx0, ALPHA * fx1);
        __half2 a1 = __floats2half2_rn(ALPHA * fx2, ALPHA * fx3);
        __half2 a2 = __floats2half2_rn(ALPHA * fx4, ALPHA * fx5);
        __half2 a3 = __floats2half2_rn(ALPHA * fx6, ALPHA * fx7);
        uint4 av;
        av.x = *reinterpret_cast<unsigned int*>(&a0);
        av.y = *reinterpret_cast<unsigned int*>(&a1);
        av.z = *reinterpret_cast<unsigned int*>(&a2);
        av.w = *reinterpret_cast<unsigned int*>(&a3);
        ((uint4*)((char*)g_f0h + (size_t)node * ROWB))[l8] = av;
    }
    if (FO == 2) {                        // final h (fp32) for the MLP
        ((float4*)(g_F2 + (size_t)node * DF))[2 * l8]     = make_float4(fx0, fx1, fx2, fx3);
        ((float4*)(g_F2 + (size_t)node * DF))[2 * l8 + 1] = make_float4(fx4, fx5, fx6, fx7);
    }
}

// ---------------- register-tiled SGEMM: C = [relu](A[MxK] @ W[KxNC] + b) ----
template<int K, int NC, bool RELU>
__global__ __launch_bounds__(256) void gemm_tiled(const float* __restrict__ A,
                                                  const float* __restrict__ W,
                                                  const float* __restrict__ bias,
                                                  float* __restrict__ C, int M) {
    constexpr int TX = NC / 4;       // 32 (NC=128) or 16 (NC=64)
    constexpr int TY = 256 / TX;     // 8 or 16
    constexpr int TM = 64 / TY;      // 8 or 4
    __shared__ float sAT[32][66];    // [k][row]
    __shared__ float sW[32][NC];

    int tid = threadIdx.x;
    int tx = tid % TX;
    int ty = tid / TX;
    int rowBase = blockIdx.x * 64;

    float acc[TM][4];
#pragma unroll
    for (int m = 0; m < TM; m++)
#pragma unroll
        for (int j = 0; j < 4; j++) acc[m][j] = 0.0f;

    for (int kk = 0; kk < K; kk += 32) {
        for (int i = tid; i < 64 * 32; i += 256) {
            int r = i >> 5, k = i & 31;
            int gr = rowBase + r;
            sAT[k][r] = (gr < M) ? A[(size_t)gr * K + kk + k] : 0.0f;
        }
        for (int i = tid; i < 32 * NC; i += 256) {
            int k = i / NC, c = i % NC;
            sW[k][c] = W[(size_t)(kk + k) * NC + c];
        }
        __syncthreads();
#pragma unroll
        for (int k = 0; k < 32; k++) {
            float4 w = *(const float4*)&sW[k][tx * 4];
            float a[TM];
#pragma unroll
            for (int m2 = 0; m2 < TM / 2; m2++) {
                float2 t = *(const float2*)&sAT[k][ty * TM + 2 * m2];
                a[2 * m2] = t.x; a[2 * m2 + 1] = t.y;
            }
#pragma unroll
            for (int m = 0; m < TM; m++) {
                acc[m][0] += a[m] * w.x;
                acc[m][1] += a[m] * w.y;
                acc[m][2] += a[m] * w.z;
                acc[m][3] += a[m] * w.w;
            }
        }
        __syncthreads();
    }

    float4 bv = *(const float4*)&bias[tx * 4];
#pragma unroll
    for (int m = 0; m < TM; m++) {
        int gr = rowBase + ty * TM + m;
        if (gr < M) {
            float4 v;
            v.x = acc[m][0] + bv.x;
            v.y = acc[m][1] + bv.y;
            v.z = acc[m][2] + bv.z;
            v.w = acc[m][3] + bv.w;
            if (RELU) {
                v.x = fmaxf(v.x, 0.0f); v.y = fmaxf(v.y, 0.0f);
                v.z = fmaxf(v.z, 0.0f); v.w = fmaxf(v.w, 0.0f);
            }
            *(float4*)&C[(size_t)gr * NC + tx * 4] = v;
        }
    }
}

// naive GEMM kept for the small head layer (K=64, NC=40)
template<int K, int NC, bool RELU>
__global__ __launch_bounds__(256) void gemm_small(const float* __restrict__ A,
                                                  const float* __restrict__ W,
                                                  const float* __restrict__ bias,
                                                  float* __restrict__ C, int M) {
    __shared__ float sA[64][33];
    __shared__ float sW[32][NC];
    const int CPT = NC / 4;
    float acc[CPT];
    int tid = threadIdx.x;
    int r  = tid >> 2;
    int cg = tid & 3;
    int row = blockIdx.x * 64 + r;
#pragma unroll
    for (int c = 0; c < CPT; c++) acc[c] = 0.0f;

    for (int kk = 0; kk < K; kk += 32) {
        for (int i = tid; i < 64 * 32; i += 256) {
            int rr = i >> 5, kx = i & 31;
            int grow = blockIdx.x * 64 + rr;
            sA[rr][kx] = (grow < M) ? A[(size_t)grow * K + kk + kx] : 0.0f;
        }
        for (int i = tid; i < 32 * NC; i += 256) {
            int kx = i / NC, cx = i % NC;
            sW[kx][cx] = W[(size_t)(kk + kx) * NC + cx];
        }
        __syncthreads();
#pragma unroll
        for (int k = 0; k < 32; k++) {
            float a = sA[r][k];
#pragma unroll
            for (int c = 0; c < CPT; c++) acc[c] += a * sW[k][c * 4 + cg];
        }
        __syncthreads();
    }

    if (row < M) {
#pragma unroll
        for (int c = 0; c < CPT; c++) {
            float v = acc[c] + bias[c * 4 + cg];
            if (RELU) v = fmaxf(v, 0.0f);
            C[(size_t)row * NC + c * 4 + cg] = v;
        }
    }
}

// ---------------- launch ----------------------------------------------------
extern "C" void kernel_launch(void* const* d_in, const int* in_sizes, int n_in,
                              void* d_out, int out_size) {
    const float* feat = (const float*)d_in[0];
    const int*   src  = (const int*)  d_in[1];
    const int*   dst  = (const int*)  d_in[2];
    const float* W1   = (const float*)d_in[3];
    const float* b1   = (const float*)d_in[4];
    const float* W2   = (const float*)d_in[5];
    const float* b2   = (const float*)d_in[6];
    const float* Wh1  = (const float*)d_in[7];
    const float* bh1  = (const float*)d_in[8];
    const float* Wh2  = (const float*)d_in[9];
    const float* bh2  = (const float*)d_in[10];
    float* out = (float*)d_out;

    int n = in_sizes[0] / DF;
    int e = in_sizes[1];

    void *pF2, *pFa, *pFb, *pT1, *pT2;
    cudaGetSymbolAddress(&pF2, g_F2);
    cudaGetSymbolAddress(&pFa, g_FSa);
    cudaGetSymbolAddress(&pFb, g_FSb);
    cudaGetSymbolAddress(&pT1, g_t1);
    cudaGetSymbolAddress(&pT2, g_t2);
    float*   F2  = (float*)pF2;
    __half2* FSa = (__half2*)pFa;
    __half2* FSb = (__half2*)pFb;
    float*   T1  = (float*)pT1;
    float*   T2  = (float*)pT2;

    // exact one co-resident wave for finalize's internal grid barrier
    int dev = 0, sms = 0, occ = 0;
    cudaGetDevice(&dev);
    cudaDeviceGetAttribute(&sms, cudaDevAttrMultiProcessorCount, dev);
    cudaOccupancyMaxActiveBlocksPerMultiprocessor(&occ, finalize_kernel, 256, 0);
    if (occ < 1) occ = 1;
    int fblocks = sms * occ;

    // --- preprocessing: exactly 3 launches (4th launch = appnp_step #0) ---
    zero_kernel    <<<(n + 255) / 256, 256>>>(n);
    deg_kernel     <<<(e + 255) / 256, 256>>>(src, dst, e);
    finalize_kernel<<<fblocks, 256>>>(src, dst, feat, n, e);

    // --- 20 propagation steps (2 APPNP phases of K=10) ---
    int step_blocks = (n + 31) / 32;  // 32 quarter-warps (nodes) per 256-thread block
    __half2* fin = FSa; __half2* fout = FSb;
    for (int s = 0; s < 20; s++) {
        if      (s == 9)  appnp_step<1><<<step_blocks, 256>>>(fin, fout, n);
        else if (s == 19) appnp_step<2><<<step_blocks, 256>>>(fin, fout, n);
        else              appnp_step<0><<<step_blocks, 256>>>(fin, fout, n);
        __half2* t = fin; fin = fout; fout = t;
    }

    // --- MLP trunk + head (fp32 SGEMMs) ---
    float* h_last = out + (size_t)n * CCH;   // d_out = [out (N*40)] [h_last (N*128)]
    int gb = (n + 63) / 64;
    gemm_tiled<DF,  HH,  true ><<<gb, 256>>>(F2,     W1,  b1,  T1,     n);
    gemm_tiled<HH,  HH,  false><<<gb, 256>>>(T1,     W2,  b2,  h_last, n);
    gemm_tiled<HH,  HHF, true ><<<gb, 256>>>(h_last, Wh1, bh1, T2,     n);
    gemm_small<HHF, CCH, false><<<gb, 256>>>(T2,     Wh2, bh2, out,    n);
}